// round 2
// baseline (speedup 1.0000x reference)
#include <cuda_runtime.h>
#include <cuda_bf16.h>
#include <cstddef>
#include <math.h>

// ---------------------------------------------------------------------------
// PCDAlign fp32, FFMA2 (fma.rn.f32x2) everywhere.
//   conv3_k  : 3x3 conv pad1, 32x32 px tile, 4 px/thread (2 packed pairs),
//              CO_BLK outs/thread, weights duplicated {w,w} in smem (LDS.64).
//   up2_k    : bilinear 2x upsample * scale.
//   dcn_sample_k : modulated deformable bilinear sampling -> samp[b][576][HW]
//   gemm576_k    : out[64,HW] = W[64,576] @ samp  (+bias, opt lrelu), FFMA2.
// ---------------------------------------------------------------------------

#define NF 64

typedef unsigned long long u64;

__device__ __forceinline__ u64 pk2(float lo, float hi) {
    u64 r;
    asm("mov.b64 %0, {%1, %2};" : "=l"(r)
        : "r"(__float_as_uint(lo)), "r"(__float_as_uint(hi)));
    return r;
}
__device__ __forceinline__ void upk2(u64 v, float& lo, float& hi) {
    unsigned a, b;
    asm("mov.b64 {%0, %1}, %2;" : "=r"(a), "=r"(b) : "l"(v));
    lo = __uint_as_float(a); hi = __uint_as_float(b);
}
__device__ __forceinline__ u64 fma2(u64 a, u64 b, u64 c) {
    u64 d;
    asm("fma.rn.f32x2 %0, %1, %2, %3;" : "=l"(d) : "l"(a), "l"(b), "l"(c));
    return d;
}

// scratch (B=4 fixed)
#define L1N (4*64*128*128)
#define L2N (4*64*64*64)
#define L3N (4*64*32*32)
#define OMN (4*216*128*128)
#define SAMPN (4*576*128*128)

__device__ float g_A [L1N];
__device__ float g_B [L1N];
__device__ float g_C [L1N];
__device__ float g_D [L1N];
__device__ float g_UP[L1N];
__device__ float g_OM[OMN];
__device__ float g_SAMP[SAMPN];
__device__ float g_L3o[L3N];
__device__ float g_L3f[L3N];
__device__ float g_L2o[L2N];
__device__ float g_L2f[L2N];

// ---------------------------------------------------------------------------
// conv3: 32x32 pixel tile, 256 threads, 4 px/thread (one row chunk of 4).
// Input channels in chunks of 4 via smem. Weights as float2 {w,w}.
// ---------------------------------------------------------------------------
template<int CO_BLK>
__global__ __launch_bounds__(256)
void conv3_k(const float* __restrict__ in1, const float* __restrict__ in2,
             const float* __restrict__ wt,  const float* __restrict__ bs,
             float* __restrict__ out,
             int H, int W, int Cin, int C1, int Cout, int act)
{
    const int tilesX = W >> 5;
    const int tx0 = (blockIdx.x % tilesX) << 5;
    const int ty0 = (blockIdx.x / tilesX) << 5;
    const int b   = blockIdx.y;
    const int co0 = blockIdx.z * CO_BLK;
    const int tid = threadIdx.x;
    const int px0 = (tid & 7) << 2;    // 0,4,...,28
    const int py  = tid >> 3;          // 0..31
    const int HW  = H * W;
    const int C2  = Cin - C1;

    __shared__ float  sIn[4][34*35];       // 34 rows, stride 35 (conflict-free)
    __shared__ float2 sW [CO_BLK*36];      // {w,w} pairs

    u64 acc[CO_BLK][2];
#pragma unroll
    for (int i = 0; i < CO_BLK; i++) { acc[i][0] = 0ULL; acc[i][1] = 0ULL; }

    for (int c0 = 0; c0 < Cin; c0 += 4) {
        __syncthreads();
        // input patches 34x34, zero-padded
        for (int idx = tid; idx < 4*34*34; idx += 256) {
            int ci = idx / 1156;
            int r  = idx - ci*1156;
            int pr = r / 34, pc = r - pr*34;
            int gy = ty0 - 1 + pr, gx = tx0 - 1 + pc;
            float v = 0.f;
            if ((unsigned)gy < (unsigned)H && (unsigned)gx < (unsigned)W) {
                int c = c0 + ci;
                const float* src = (c < C1)
                    ? in1 + ((size_t)b*C1 + c     ) * HW
                    : in2 + ((size_t)b*C2 + (c-C1)) * HW;
                v = src[gy*W + gx];
            }
            sIn[ci][pr*35 + pc] = v;
        }
        // weights: sW[co*36 + ci*9 + k] = {w,w}
        for (int idx = tid; idx < CO_BLK*36; idx += 256) {
            int co = idx / 36, rem = idx - co*36;
            int ci = rem / 9, k = rem - ci*9;
            float w = wt[((size_t)(co0+co)*Cin + (c0+ci))*9 + k];
            sW[idx] = make_float2(w, w);
        }
        __syncthreads();

#pragma unroll
        for (int ci = 0; ci < 4; ci++) {
            float s[3][6];
#pragma unroll
            for (int r = 0; r < 3; r++)
#pragma unroll
                for (int c = 0; c < 6; c++)
                    s[r][c] = sIn[ci][(py + r)*35 + px0 + c];
            u64 p[3][5];
#pragma unroll
            for (int r = 0; r < 3; r++)
#pragma unroll
                for (int j = 0; j < 5; j++)
                    p[r][j] = pk2(s[r][j], s[r][j+1]);

#pragma unroll
            for (int co = 0; co < CO_BLK; co++) {
                const u64* wp = reinterpret_cast<const u64*>(&sW[co*36 + ci*9]);
                u64 a0 = acc[co][0], a1 = acc[co][1];
#pragma unroll
                for (int kh = 0; kh < 3; kh++)
#pragma unroll
                    for (int kw = 0; kw < 3; kw++) {
                        u64 w2 = wp[kh*3 + kw];
                        a0 = fma2(p[kh][kw],   w2, a0);
                        a1 = fma2(p[kh][kw+2], w2, a1);
                    }
                acc[co][0] = a0; acc[co][1] = a1;
            }
        }
    }

    const int y = ty0 + py, x = tx0 + px0;
#pragma unroll
    for (int co = 0; co < CO_BLK; co++) {
        float bv = __ldg(bs + co0 + co);
        float v0, v1, v2, v3;
        upk2(acc[co][0], v0, v1);
        upk2(acc[co][1], v2, v3);
        v0 += bv; v1 += bv; v2 += bv; v3 += bv;
        if (act) {
            v0 = v0 >= 0.f ? v0 : 0.1f*v0;
            v1 = v1 >= 0.f ? v1 : 0.1f*v1;
            v2 = v2 >= 0.f ? v2 : 0.1f*v2;
            v3 = v3 >= 0.f ? v3 : 0.1f*v3;
        }
        size_t base = (((size_t)b*Cout + co0 + co)*H + y)*W + x;
        *reinterpret_cast<float4*>(out + base) = make_float4(v0, v1, v2, v3);
    }
}

// ---------------------------------------------------------------------------
// bilinear 2x upsample (align_corners=False), * scale
// ---------------------------------------------------------------------------
__global__ void up2_k(const float* __restrict__ in, float* __restrict__ out,
                      int NC, int H, int W, float scale)
{
    const int W2 = 2*W, H2 = 2*H;
    size_t idx = (size_t)blockIdx.x * blockDim.x + threadIdx.x;
    size_t total = (size_t)NC * H2 * W2;
    if (idx >= total) return;
    int x2 = (int)(idx % W2);
    int y2 = (int)((idx / W2) % H2);
    int c  = (int)(idx / ((size_t)W2 * H2));

    float sy = (y2 + 0.5f)*0.5f - 0.5f;
    float sx = (x2 + 0.5f)*0.5f - 0.5f;
    float fy = floorf(sy), fx = floorf(sx);
    float wy = sy - fy,    wx = sx - fx;
    int y0 = (int)fy, x0 = (int)fx;
    int y0c = min(max(y0, 0), H-1), y1c = min(max(y0+1, 0), H-1);
    int x0c = min(max(x0, 0), W-1), x1c = min(max(x0+1, 0), W-1);

    const float* img = in + (size_t)c*H*W;
    float v00 = img[y0c*W + x0c];
    float v01 = img[y0c*W + x1c];
    float v10 = img[y1c*W + x0c];
    float v11 = img[y1c*W + x1c];
    float v = (1.f-wy)*((1.f-wx)*v00 + wx*v01) + wy*((1.f-wx)*v10 + wx*v11);
    out[idx] = v * scale;
}

// ---------------------------------------------------------------------------
// DCN stage 1: modulated deformable bilinear sampling.
//   x   : [B,64,H,W]    om : [B,216,H,W]  (o1 | o2 | mask logits)
//   samp: [B,576,HW], row index = c*9 + k  (c = g*8+cc)
// grid: (HW/256, 72, B), block 256
// ---------------------------------------------------------------------------
__global__ __launch_bounds__(256)
void dcn_sample_k(const float* __restrict__ x, const float* __restrict__ om,
                  float* __restrict__ samp, int H, int W)
{
    const int HW = H * W;
    const int px = blockIdx.x * 256 + threadIdx.x;
    const int gk = blockIdx.y;
    const int b  = blockIdx.z;
    const int g  = gk / 9, k = gk - g*9;

    const float* omb = om + (size_t)b*216*HW + px;
    float oy = __ldg(omb + (size_t)gk       *HW);
    float ox = __ldg(omb + (size_t)(72 +gk) *HW);
    float mk = __ldg(omb + (size_t)(144+gk) *HW);
    mk = 1.f / (1.f + expf(-mk));

    const int hr = px / W, wc = px - hr*W;
    float py = oy + (float)(k/3 - 1) + (float)hr;
    float pv = ox + (float)(k%3 - 1) + (float)wc;
    float fy = floorf(py), fx = floorf(pv);
    float wy = py - fy,    wx = pv - fx;
    int y0 = (int)fy, x0 = (int)fx;
    int y1 = y0 + 1,  x1 = x0 + 1;
    float vy0 = (y0 >= 0 && y0 < H) ? 1.f : 0.f;
    float vy1 = (y1 >= 0 && y1 < H) ? 1.f : 0.f;
    float vx0 = (x0 >= 0 && x0 < W) ? 1.f : 0.f;
    float vx1 = (x1 >= 0 && x1 < W) ? 1.f : 0.f;
    float b00 = mk * (1.f-wy)*(1.f-wx) * vy0*vx0;
    float b01 = mk * (1.f-wy)*wx       * vy0*vx1;
    float b10 = mk * wy*(1.f-wx)       * vy1*vx0;
    float b11 = mk * wy*wx             * vy1*vx1;
    int cy0 = min(max(y0,0),H-1), cy1 = min(max(y1,0),H-1);
    int cx0 = min(max(x0,0),W-1), cx1 = min(max(x1,0),W-1);
    int o00 = cy0*W + cx0, o01 = cy0*W + cx1;
    int o10 = cy1*W + cx0, o11 = cy1*W + cx1;

    const float* xg = x + ((size_t)b*64 + g*8)*HW;
    float* sp = samp + ((size_t)b*576 + (size_t)(g*8)*9 + k)*HW + px;
#pragma unroll
    for (int cc = 0; cc < 8; cc++) {
        const float* img = xg + (size_t)cc*HW;
        float v = b00*__ldg(img+o00) + b01*__ldg(img+o01)
                + b10*__ldg(img+o10) + b11*__ldg(img+o11);
        sp[(size_t)cc*9*HW] = v;
    }
}

// ---------------------------------------------------------------------------
// DCN stage 2: out[b,64,HW] = W[64,576] @ samp[b,576,HW] + bias (opt lrelu)
// block 256 thr, 1024 px tile (4 px/thread), CO_BLK outs/thread.
// grid: (HW/1024, B, 64/CO_BLK)
// ---------------------------------------------------------------------------
template<int CO_BLK>
__global__ __launch_bounds__(256)
void gemm576_k(const float* __restrict__ samp, const float* __restrict__ wt,
               const float* __restrict__ bs, float* __restrict__ out,
               int HW, int act)
{
    const int tid = threadIdx.x;
    const int b   = blockIdx.y;
    const int co0 = blockIdx.z * CO_BLK;
    const int pxb = blockIdx.x * 1024;

    __shared__ float  sS[4][1024];
    __shared__ float2 sW[CO_BLK*4];

    u64 acc[CO_BLK][2];
#pragma unroll
    for (int i = 0; i < CO_BLK; i++) { acc[i][0] = 0ULL; acc[i][1] = 0ULL; }

    const float* sb = samp + (size_t)b*576*HW + pxb;

    for (int k0 = 0; k0 < 576; k0 += 4) {
        __syncthreads();
#pragma unroll
        for (int r = 0; r < 4; r++) {
            const float4* src = reinterpret_cast<const float4*>(sb + (size_t)(k0+r)*HW);
            reinterpret_cast<float4*>(sS[r])[tid] = src[tid];
        }
        if (tid < CO_BLK*4) {
            int co = tid >> 2, k = tid & 3;
            float w = __ldg(wt + (size_t)(co0+co)*576 + k0 + k);
            sW[tid] = make_float2(w, w);
        }
        __syncthreads();

#pragma unroll
        for (int r = 0; r < 4; r++) {
            u64 s0 = *reinterpret_cast<const u64*>(&sS[r][tid*4]);
            u64 s1 = *reinterpret_cast<const u64*>(&sS[r][tid*4 + 2]);
#pragma unroll
            for (int co = 0; co < CO_BLK; co++) {
                u64 w2 = *reinterpret_cast<const u64*>(&sW[co*4 + r]);
                acc[co][0] = fma2(s0, w2, acc[co][0]);
                acc[co][1] = fma2(s1, w2, acc[co][1]);
            }
        }
    }

    const int px = pxb + tid*4;
#pragma unroll
    for (int co = 0; co < CO_BLK; co++) {
        float bv = __ldg(bs + co0 + co);
        float v0, v1, v2, v3;
        upk2(acc[co][0], v0, v1);
        upk2(acc[co][1], v2, v3);
        v0 += bv; v1 += bv; v2 += bv; v3 += bv;
        if (act) {
            v0 = v0 >= 0.f ? v0 : 0.1f*v0;
            v1 = v1 >= 0.f ? v1 : 0.1f*v1;
            v2 = v2 >= 0.f ? v2 : 0.1f*v2;
            v3 = v3 >= 0.f ? v3 : 0.1f*v3;
        }
        *reinterpret_cast<float4*>(out + ((size_t)b*64 + co0 + co)*HW + px)
            = make_float4(v0, v1, v2, v3);
    }
}

// ---------------------------------------------------------------------------
// host orchestration
// ---------------------------------------------------------------------------
static void conv3(const float* i1, const float* i2, const float* w, const float* b_,
                  float* o, int B, int H, int W, int Cin, int C1, int Cout, int act)
{
    dim3 blk(256);
    dim3 grid((W>>5)*(H>>5), B, 0);
    if (Cout == 216) {
        grid.z = 216/12;
        conv3_k<12><<<grid, blk>>>(i1, i2, w, b_, o, H, W, Cin, C1, Cout, act);
    } else {
        grid.z = Cout/16;
        conv3_k<16><<<grid, blk>>>(i1, i2, w, b_, o, H, W, Cin, C1, Cout, act);
    }
}

static void up2(const float* in, float* out, int B, int C, int H, int W, float scale)
{
    size_t n = (size_t)B*C*2*H*2*W;
    int blocks = (int)((n + 255) / 256);
    up2_k<<<blocks, 256>>>(in, out, B*C, H, W, scale);
}

static void dcn(const float* x, const float* om, float* sampbuf,
                const float* w, const float* b_,
                float* out, int B, int H, int W, int act)
{
    int HW = H*W;
    dim3 sg(HW/256, 72, B);
    dcn_sample_k<<<sg, 256>>>(x, om, sampbuf, H, W);
    if (HW >= 4096) {
        dim3 gg(HW/1024, B, 4);
        gemm576_k<16><<<gg, 256>>>(sampbuf, w, b_, out, HW, act);
    } else {
        dim3 gg(HW/1024, B, 8);
        gemm576_k<8><<<gg, 256>>>(sampbuf, w, b_, out, HW, act);
    }
}

extern "C" void kernel_launch(void* const* d_in, const int* in_sizes, int n_in,
                              void* d_out, int out_size)
{
    const float* f1l1 = (const float*)d_in[0];
    const float* f1l2 = (const float*)d_in[1];
    const float* f1l3 = (const float*)d_in[2];
    const float* f2l1 = (const float*)d_in[3];
    const float* f2l2 = (const float*)d_in[4];
    const float* f2l3 = (const float*)d_in[5];
    const float* w128 = (const float*)d_in[6];
    const float* b128 = (const float*)d_in[7];
    const float* w64  = (const float*)d_in[8];
    const float* b64  = (const float*)d_in[9];
    const float* om_w = (const float*)d_in[10];
    const float* om_b = (const float*)d_in[11];
    const float* dw   = (const float*)d_in[12];
    const float* db   = (const float*)d_in[13];
    float* outp = (float*)d_out;

    const int B = in_sizes[0] / (NF*128*128);   // 4

    float *gA,*gB,*gC,*gD,*gUP,*gOM,*gSP,*gL3o,*gL3f,*gL2o,*gL2f;
    cudaGetSymbolAddress((void**)&gA,  g_A);
    cudaGetSymbolAddress((void**)&gB,  g_B);
    cudaGetSymbolAddress((void**)&gC,  g_C);
    cudaGetSymbolAddress((void**)&gD,  g_D);
    cudaGetSymbolAddress((void**)&gUP, g_UP);
    cudaGetSymbolAddress((void**)&gOM, g_OM);
    cudaGetSymbolAddress((void**)&gSP, g_SAMP);
    cudaGetSymbolAddress((void**)&gL3o, g_L3o);
    cudaGetSymbolAddress((void**)&gL3f, g_L3f);
    cudaGetSymbolAddress((void**)&gL2o, g_L2o);
    cudaGetSymbolAddress((void**)&gL2f, g_L2f);

    const size_t W128S = (size_t)64*128*9, B128S = 64;
    const size_t W64S  = (size_t)64*64*9,  B64S  = 64;
    const size_t OMWS  = (size_t)216*64*9, OMBS  = 216;
    const size_t DWS   = (size_t)64*64*9,  DBS   = 64;

    // ---- L3 (32x32) ----
    conv3(f1l3, f2l3, w128+0*W128S, b128+0*B128S, gA,  B, 32, 32, 128, 64, 64, 1);
    conv3(gA, nullptr, w64+0*W64S,  b64+0*B64S,   gL3o,B, 32, 32,  64, 64, 64, 1);
    conv3(gL3o, nullptr, om_w+0*OMWS, om_b+0*OMBS, gOM, B, 32, 32, 64, 64, 216, 0);
    dcn(f1l3, gOM, gSP, dw+0*DWS, db+0*DBS, gL3f, B, 32, 32, 1);

    // ---- L2 (64x64) ----
    conv3(f1l2, f2l2, w128+1*W128S, b128+1*B128S, gA,  B, 64, 64, 128, 64, 64, 1);
    up2(gL3o, gUP, B, 64, 32, 32, 2.0f);
    conv3(gA, gUP, w128+2*W128S, b128+2*B128S, gB,  B, 64, 64, 128, 64, 64, 1);
    conv3(gB, nullptr, w64+1*W64S, b64+1*B64S, gL2o, B, 64, 64, 64, 64, 64, 1);
    conv3(gL2o, nullptr, om_w+1*OMWS, om_b+1*OMBS, gOM, B, 64, 64, 64, 64, 216, 0);
    dcn(f1l2, gOM, gSP, dw+1*DWS, db+1*DBS, gA, B, 64, 64, 0);
    up2(gL3f, gUP, B, 64, 32, 32, 1.0f);
    conv3(gA, gUP, w128+3*W128S, b128+3*B128S, gL2f, B, 64, 64, 128, 64, 64, 1);

    // ---- L1 (128x128) ----
    conv3(f1l1, f2l1, w128+4*W128S, b128+4*B128S, gA,  B, 128, 128, 128, 64, 64, 1);
    up2(gL2o, gUP, B, 64, 64, 64, 2.0f);
    conv3(gA, gUP, w128+5*W128S, b128+5*B128S, gB,  B, 128, 128, 128, 64, 64, 1);
    conv3(gB, nullptr, w64+2*W64S, b64+2*B64S, gC,  B, 128, 128, 64, 64, 64, 1);
    conv3(gC, nullptr, om_w+2*OMWS, om_b+2*OMBS, gOM, B, 128, 128, 64, 64, 216, 0);
    dcn(f1l1, gOM, gSP, dw+2*DWS, db+2*DBS, gA, B, 128, 128, 0);
    up2(gL2f, gUP, B, 64, 64, 64, 1.0f);
    conv3(gA, gUP, w128+6*W128S, b128+6*B128S, gD,  B, 128, 128, 128, 64, 64, 0);

    // ---- Cascading ----
    conv3(gD, f2l1, w128+7*W128S, b128+7*B128S, gA, B, 128, 128, 128, 64, 64, 1);
    conv3(gA, nullptr, w64+3*W64S, b64+3*B64S, gB, B, 128, 128, 64, 64, 64, 1);
    conv3(gB, nullptr, om_w+3*OMWS, om_b+3*OMBS, gOM, B, 128, 128, 64, 64, 216, 0);
    dcn(gD, gOM, gSP, dw+3*DWS, db+3*DBS, outp, B, 128, 128, 1);
}

// round 4
// speedup vs baseline: 1.0512x; 1.0512x over previous
#include <cuda_runtime.h>
#include <cuda_bf16.h>
#include <cstddef>
#include <math.h>

// ---------------------------------------------------------------------------
// PCDAlign fp32. FFMA2 (fma.rn.f32x2) convs with bounded registers.
//   conv3_k<TW>  : 3x3 conv pad1. Tile TW x (1024/TW) pixels, 256 threads,
//                  4 px/thread, CO_BLK=8 output channels/block.
//   up2_k        : bilinear 2x upsample * scale.
//   dcn_sample_k : modulated deformable bilinear sampling -> samp[b][576][HW]
//   gemm576_k    : out[64,HW] = W[64,576] @ samp (+bias, opt lrelu), FFMA2.
// ---------------------------------------------------------------------------

#define NF 64
#define CO_BLK 8

typedef unsigned long long u64;

__device__ __forceinline__ u64 pk2(float lo, float hi) {
    u64 r;
    asm("mov.b64 %0, {%1, %2};" : "=l"(r)
        : "r"(__float_as_uint(lo)), "r"(__float_as_uint(hi)));
    return r;
}
__device__ __forceinline__ void upk2(u64 v, float& lo, float& hi) {
    unsigned a, b;
    asm("mov.b64 {%0, %1}, %2;" : "=r"(a), "=r"(b) : "l"(v));
    lo = __uint_as_float(a); hi = __uint_as_float(b);
}
__device__ __forceinline__ u64 fma2(u64 a, u64 b, u64 c) {
    u64 d;
    asm("fma.rn.f32x2 %0, %1, %2, %3;" : "=l"(d) : "l"(a), "l"(b), "l"(c));
    return d;
}

// scratch (B=4 fixed)
#define L1N (4*64*128*128)
#define L2N (4*64*64*64)
#define L3N (4*64*32*32)
#define OMN (4*216*128*128)
#define SAMPN (4*576*128*128)

__device__ float g_A [L1N];
__device__ float g_B [L1N];
__device__ float g_C [L1N];
__device__ float g_D [L1N];
__device__ float g_UP[L1N];
__device__ float g_OM[OMN];
__device__ float g_SAMP[SAMPN];
__device__ float g_L3o[L3N];
__device__ float g_L3f[L3N];
__device__ float g_L2o[L2N];
__device__ float g_L2f[L2N];

// ---------------------------------------------------------------------------
// conv3: TW x TH tile (TW*TH = 1024), 256 threads, 4 px/thread.
// Input channels in chunks of 4 via smem; weights duplicated {w,w} in smem.
// ---------------------------------------------------------------------------
template<int TW>
__global__ __launch_bounds__(256, 2)
void conv3_k(const float* __restrict__ in1, const float* __restrict__ in2,
             const float* __restrict__ wt,  const float* __restrict__ bs,
             float* __restrict__ out,
             int H, int W, int Cin, int C1, int Cout, int act)
{
    constexpr int TH = 1024 / TW;
    constexpr int PR = TH + 2;          // patch rows
    constexpr int PC = TW + 2;          // patch cols
    constexpr int PS = TW + 4;          // patch row stride
    const int tilesX = W / TW;
    const int tx0 = (blockIdx.x % tilesX) * TW;
    const int ty0 = (blockIdx.x / tilesX) * TH;
    const int b   = blockIdx.y;
    const int co0 = blockIdx.z * CO_BLK;
    const int tid = threadIdx.x;
    const int px0 = (tid % (TW/4)) * 4;
    const int py  = tid / (TW/4);
    const int HW  = H * W;
    const int C2  = Cin - C1;

    __shared__ float  sIn[4][PR*PS];
    __shared__ float2 sW [CO_BLK*36];

    u64 acc[CO_BLK][2];
#pragma unroll
    for (int i = 0; i < CO_BLK; i++) { acc[i][0] = 0ULL; acc[i][1] = 0ULL; }

    for (int c0 = 0; c0 < Cin; c0 += 4) {
        __syncthreads();
        // input patches PRxPC, zero-padded at image borders
        for (int idx = tid; idx < 4*PR*PC; idx += 256) {
            int ci = idx / (PR*PC);
            int r  = idx - ci*(PR*PC);
            int pr = r / PC, pc = r - pr*PC;
            int gy = ty0 - 1 + pr, gx = tx0 - 1 + pc;
            float v = 0.f;
            if ((unsigned)gy < (unsigned)H && (unsigned)gx < (unsigned)W) {
                int c = c0 + ci;
                const float* src = (c < C1)
                    ? in1 + ((size_t)b*C1 + c     ) * HW
                    : in2 + ((size_t)b*C2 + (c-C1)) * HW;
                v = src[gy*W + gx];
            }
            sIn[ci][pr*PS + pc] = v;
        }
        // weights: sW[co*36 + ci*9 + k] = {w,w}  (CO_BLK*36 = 288 > 256 -> loop!)
        for (int idx = tid; idx < CO_BLK*36; idx += 256) {
            int co = idx / 36, rem = idx - co*36;
            int ci = rem / 9, k = rem - ci*9;
            float w = wt[((size_t)(co0+co)*Cin + (c0+ci))*9 + k];
            sW[idx] = make_float2(w, w);
        }
        __syncthreads();

#pragma unroll
        for (int ci = 0; ci < 4; ci++) {
            u64 p[3][5];
#pragma unroll
            for (int r = 0; r < 3; r++) {
                float s0 = sIn[ci][(py+r)*PS + px0 + 0];
                float s1 = sIn[ci][(py+r)*PS + px0 + 1];
                float s2 = sIn[ci][(py+r)*PS + px0 + 2];
                float s3 = sIn[ci][(py+r)*PS + px0 + 3];
                float s4 = sIn[ci][(py+r)*PS + px0 + 4];
                float s5 = sIn[ci][(py+r)*PS + px0 + 5];
                p[r][0] = pk2(s0, s1);
                p[r][1] = pk2(s1, s2);
                p[r][2] = pk2(s2, s3);
                p[r][3] = pk2(s3, s4);
                p[r][4] = pk2(s4, s5);
            }
#pragma unroll
            for (int co = 0; co < CO_BLK; co++) {
                const u64* wp = reinterpret_cast<const u64*>(&sW[co*36 + ci*9]);
                u64 a0 = acc[co][0], a1 = acc[co][1];
#pragma unroll
                for (int kh = 0; kh < 3; kh++)
#pragma unroll
                    for (int kw = 0; kw < 3; kw++) {
                        u64 w2 = wp[kh*3 + kw];
                        a0 = fma2(p[kh][kw],   w2, a0);
                        a1 = fma2(p[kh][kw+2], w2, a1);
                    }
                acc[co][0] = a0; acc[co][1] = a1;
            }
        }
    }

    const int y = ty0 + py, x = tx0 + px0;
#pragma unroll
    for (int co = 0; co < CO_BLK; co++) {
        float bv = __ldg(bs + co0 + co);
        float v0, v1, v2, v3;
        upk2(acc[co][0], v0, v1);
        upk2(acc[co][1], v2, v3);
        v0 += bv; v1 += bv; v2 += bv; v3 += bv;
        if (act) {
            v0 = v0 >= 0.f ? v0 : 0.1f*v0;
            v1 = v1 >= 0.f ? v1 : 0.1f*v1;
            v2 = v2 >= 0.f ? v2 : 0.1f*v2;
            v3 = v3 >= 0.f ? v3 : 0.1f*v3;
        }
        size_t base = (((size_t)b*Cout + co0 + co)*H + y)*W + x;
        *reinterpret_cast<float4*>(out + base) = make_float4(v0, v1, v2, v3);
    }
}

// ---------------------------------------------------------------------------
// bilinear 2x upsample (align_corners=False), * scale
// ---------------------------------------------------------------------------
__global__ void up2_k(const float* __restrict__ in, float* __restrict__ out,
                      int NC, int H, int W, float scale)
{
    const int W2 = 2*W, H2 = 2*H;
    size_t idx = (size_t)blockIdx.x * blockDim.x + threadIdx.x;
    size_t total = (size_t)NC * H2 * W2;
    if (idx >= total) return;
    int x2 = (int)(idx % W2);
    int y2 = (int)((idx / W2) % H2);
    int c  = (int)(idx / ((size_t)W2 * H2));

    float sy = (y2 + 0.5f)*0.5f - 0.5f;
    float sx = (x2 + 0.5f)*0.5f - 0.5f;
    float fy = floorf(sy), fx = floorf(sx);
    float wy = sy - fy,    wx = sx - fx;
    int y0 = (int)fy, x0 = (int)fx;
    int y0c = min(max(y0, 0), H-1), y1c = min(max(y0+1, 0), H-1);
    int x0c = min(max(x0, 0), W-1), x1c = min(max(x0+1, 0), W-1);

    const float* img = in + (size_t)c*H*W;
    float v00 = img[y0c*W + x0c];
    float v01 = img[y0c*W + x1c];
    float v10 = img[y1c*W + x0c];
    float v11 = img[y1c*W + x1c];
    float v = (1.f-wy)*((1.f-wx)*v00 + wx*v01) + wy*((1.f-wx)*v10 + wx*v11);
    out[idx] = v * scale;
}

// ---------------------------------------------------------------------------
// DCN stage 1: modulated deformable bilinear sampling.
//   x : [B,64,H,W]   om : [B,216,H,W]   samp : [B,576,HW] row = c*9+k
// ---------------------------------------------------------------------------
__global__ __launch_bounds__(256)
void dcn_sample_k(const float* __restrict__ x, const float* __restrict__ om,
                  float* __restrict__ samp, int H, int W)
{
    const int HW = H * W;
    const int px = blockIdx.x * 256 + threadIdx.x;
    const int gk = blockIdx.y;
    const int b  = blockIdx.z;
    const int g  = gk / 9, k = gk - g*9;

    const float* omb = om + (size_t)b*216*HW + px;
    float oy = __ldg(omb + (size_t)gk       *HW);
    float ox = __ldg(omb + (size_t)(72 +gk) *HW);
    float mk = __ldg(omb + (size_t)(144+gk) *HW);
    mk = 1.f / (1.f + expf(-mk));

    const int hr = px / W, wc = px - hr*W;
    float py = oy + (float)(k/3 - 1) + (float)hr;
    float pv = ox + (float)(k%3 - 1) + (float)wc;
    float fy = floorf(py), fx = floorf(pv);
    float wy = py - fy,    wx = pv - fx;
    int y0 = (int)fy, x0 = (int)fx;
    int y1 = y0 + 1,  x1 = x0 + 1;
    float vy0 = (y0 >= 0 && y0 < H) ? 1.f : 0.f;
    float vy1 = (y1 >= 0 && y1 < H) ? 1.f : 0.f;
    float vx0 = (x0 >= 0 && x0 < W) ? 1.f : 0.f;
    float vx1 = (x1 >= 0 && x1 < W) ? 1.f : 0.f;
    float b00 = mk * (1.f-wy)*(1.f-wx) * vy0*vx0;
    float b01 = mk * (1.f-wy)*wx       * vy0*vx1;
    float b10 = mk * wy*(1.f-wx)       * vy1*vx0;
    float b11 = mk * wy*wx             * vy1*vx1;
    int cy0 = min(max(y0,0),H-1), cy1 = min(max(y1,0),H-1);
    int cx0 = min(max(x0,0),W-1), cx1 = min(max(x1,0),W-1);
    int o00 = cy0*W + cx0, o01 = cy0*W + cx1;
    int o10 = cy1*W + cx0, o11 = cy1*W + cx1;

    const float* xg = x + ((size_t)b*64 + g*8)*HW;
    float* sp = samp + ((size_t)b*576 + (size_t)(g*8)*9 + k)*HW + px;
#pragma unroll
    for (int cc = 0; cc < 8; cc++) {
        const float* img = xg + (size_t)cc*HW;
        float v = b00*__ldg(img+o00) + b01*__ldg(img+o01)
                + b10*__ldg(img+o10) + b11*__ldg(img+o11);
        sp[(size_t)cc*9*HW] = v;
    }
}

// ---------------------------------------------------------------------------
// DCN stage 2: out[b,64,HW] = W[64,576] @ samp[b,576,HW] + bias (opt lrelu)
// ---------------------------------------------------------------------------
template<int CB>
__global__ __launch_bounds__(256)
void gemm576_k(const float* __restrict__ samp, const float* __restrict__ wt,
               const float* __restrict__ bs, float* __restrict__ out,
               int HW, int act)
{
    const int tid = threadIdx.x;
    const int b   = blockIdx.y;
    const int co0 = blockIdx.z * CB;
    const int pxb = blockIdx.x * 1024;

    __shared__ float  sS[4][1024];
    __shared__ float2 sW[CB*4];

    u64 acc[CB][2];
#pragma unroll
    for (int i = 0; i < CB; i++) { acc[i][0] = 0ULL; acc[i][1] = 0ULL; }

    const float* sb = samp + (size_t)b*576*HW + pxb;

    for (int k0 = 0; k0 < 576; k0 += 4) {
        __syncthreads();
#pragma unroll
        for (int r = 0; r < 4; r++) {
            const float4* src = reinterpret_cast<const float4*>(sb + (size_t)(k0+r)*HW);
            reinterpret_cast<float4*>(sS[r])[tid] = src[tid];
        }
        if (tid < CB*4) {
            int co = tid >> 2, k = tid & 3;
            float w = __ldg(wt + (size_t)(co0+co)*576 + k0 + k);
            sW[tid] = make_float2(w, w);
        }
        __syncthreads();

#pragma unroll
        for (int r = 0; r < 4; r++) {
            u64 s0 = *reinterpret_cast<const u64*>(&sS[r][tid*4]);
            u64 s1 = *reinterpret_cast<const u64*>(&sS[r][tid*4 + 2]);
#pragma unroll
            for (int co = 0; co < CB; co++) {
                u64 w2 = *reinterpret_cast<const u64*>(&sW[co*4 + r]);
                acc[co][0] = fma2(s0, w2, acc[co][0]);
                acc[co][1] = fma2(s1, w2, acc[co][1]);
            }
        }
    }

    const int px = pxb + tid*4;
#pragma unroll
    for (int co = 0; co < CB; co++) {
        float bv = __ldg(bs + co0 + co);
        float v0, v1, v2, v3;
        upk2(acc[co][0], v0, v1);
        upk2(acc[co][1], v2, v3);
        v0 += bv; v1 += bv; v2 += bv; v3 += bv;
        if (act) {
            v0 = v0 >= 0.f ? v0 : 0.1f*v0;
            v1 = v1 >= 0.f ? v1 : 0.1f*v1;
            v2 = v2 >= 0.f ? v2 : 0.1f*v2;
            v3 = v3 >= 0.f ? v3 : 0.1f*v3;
        }
        *reinterpret_cast<float4*>(out + ((size_t)b*64 + co0 + co)*HW + px)
            = make_float4(v0, v1, v2, v3);
    }
}

// ---------------------------------------------------------------------------
// host orchestration
// ---------------------------------------------------------------------------
static void conv3(const float* i1, const float* i2, const float* w, const float* b_,
                  float* o, int B, int H, int W, int Cin, int C1, int Cout, int act)
{
    dim3 blk(256);
    if (W >= 64) {
        dim3 grid((W/64)*(H/16), B, Cout/CO_BLK);
        conv3_k<64><<<grid, blk>>>(i1, i2, w, b_, o, H, W, Cin, C1, Cout, act);
    } else {
        dim3 grid((W/32)*(H/32), B, Cout/CO_BLK);
        conv3_k<32><<<grid, blk>>>(i1, i2, w, b_, o, H, W, Cin, C1, Cout, act);
    }
}

static void up2(const float* in, float* out, int B, int C, int H, int W, float scale)
{
    size_t n = (size_t)B*C*2*H*2*W;
    int blocks = (int)((n + 255) / 256);
    up2_k<<<blocks, 256>>>(in, out, B*C, H, W, scale);
}

static void dcn(const float* x, const float* om, float* sampbuf,
                const float* w, const float* b_,
                float* out, int B, int H, int W, int act)
{
    int HW = H*W;
    dim3 sg(HW/256, 72, B);
    dcn_sample_k<<<sg, 256>>>(x, om, sampbuf, H, W);
    if (HW >= 4096) {
        dim3 gg(HW/1024, B, 4);
        gemm576_k<16><<<gg, 256>>>(sampbuf, w, b_, out, HW, act);
    } else {
        dim3 gg(HW/1024, B, 8);
        gemm576_k<8><<<gg, 256>>>(sampbuf, w, b_, out, HW, act);
    }
}

extern "C" void kernel_launch(void* const* d_in, const int* in_sizes, int n_in,
                              void* d_out, int out_size)
{
    const float* f1l1 = (const float*)d_in[0];
    const float* f1l2 = (const float*)d_in[1];
    const float* f1l3 = (const float*)d_in[2];
    const float* f2l1 = (const float*)d_in[3];
    const float* f2l2 = (const float*)d_in[4];
    const float* f2l3 = (const float*)d_in[5];
    const float* w128 = (const float*)d_in[6];
    const float* b128 = (const float*)d_in[7];
    const float* w64  = (const float*)d_in[8];
    const float* b64  = (const float*)d_in[9];
    const float* om_w = (const float*)d_in[10];
    const float* om_b = (const float*)d_in[11];
    const float* dw   = (const float*)d_in[12];
    const float* db   = (const float*)d_in[13];
    float* outp = (float*)d_out;

    const int B = in_sizes[0] / (NF*128*128);   // 4

    float *gA,*gB,*gC,*gD,*gUP,*gOM,*gSP,*gL3o,*gL3f,*gL2o,*gL2f;
    cudaGetSymbolAddress((void**)&gA,  g_A);
    cudaGetSymbolAddress((void**)&gB,  g_B);
    cudaGetSymbolAddress((void**)&gC,  g_C);
    cudaGetSymbolAddress((void**)&gD,  g_D);
    cudaGetSymbolAddress((void**)&gUP, g_UP);
    cudaGetSymbolAddress((void**)&gOM, g_OM);
    cudaGetSymbolAddress((void**)&gSP, g_SAMP);
    cudaGetSymbolAddress((void**)&gL3o, g_L3o);
    cudaGetSymbolAddress((void**)&gL3f, g_L3f);
    cudaGetSymbolAddress((void**)&gL2o, g_L2o);
    cudaGetSymbolAddress((void**)&gL2f, g_L2f);

    const size_t W128S = (size_t)64*128*9, B128S = 64;
    const size_t W64S  = (size_t)64*64*9,  B64S  = 64;
    const size_t OMWS  = (size_t)216*64*9, OMBS  = 216;
    const size_t DWS   = (size_t)64*64*9,  DBS   = 64;

    // ---- L3 (32x32) ----
    conv3(f1l3, f2l3, w128+0*W128S, b128+0*B128S, gA,  B, 32, 32, 128, 64, 64, 1);
    conv3(gA, nullptr, w64+0*W64S,  b64+0*B64S,   gL3o,B, 32, 32,  64, 64, 64, 1);
    conv3(gL3o, nullptr, om_w+0*OMWS, om_b+0*OMBS, gOM, B, 32, 32, 64, 64, 216, 0);
    dcn(f1l3, gOM, gSP, dw+0*DWS, db+0*DBS, gL3f, B, 32, 32, 1);

    // ---- L2 (64x64) ----
    conv3(f1l2, f2l2, w128+1*W128S, b128+1*B128S, gA,  B, 64, 64, 128, 64, 64, 1);
    up2(gL3o, gUP, B, 64, 32, 32, 2.0f);
    conv3(gA, gUP, w128+2*W128S, b128+2*B128S, gB,  B, 64, 64, 128, 64, 64, 1);
    conv3(gB, nullptr, w64+1*W64S, b64+1*B64S, gL2o, B, 64, 64, 64, 64, 64, 1);
    conv3(gL2o, nullptr, om_w+1*OMWS, om_b+1*OMBS, gOM, B, 64, 64, 64, 64, 216, 0);
    dcn(f1l2, gOM, gSP, dw+1*DWS, db+1*DBS, gA, B, 64, 64, 0);
    up2(gL3f, gUP, B, 64, 32, 32, 1.0f);
    conv3(gA, gUP, w128+3*W128S, b128+3*B128S, gL2f, B, 64, 64, 128, 64, 64, 1);

    // ---- L1 (128x128) ----
    conv3(f1l1, f2l1, w128+4*W128S, b128+4*B128S, gA,  B, 128, 128, 128, 64, 64, 1);
    up2(gL2o, gUP, B, 64, 64, 64, 2.0f);
    conv3(gA, gUP, w128+5*W128S, b128+5*B128S, gB,  B, 128, 128, 128, 64, 64, 1);
    conv3(gB, nullptr, w64+2*W64S, b64+2*B64S, gC,  B, 128, 128, 64, 64, 64, 1);
    conv3(gC, nullptr, om_w+2*OMWS, om_b+2*OMBS, gOM, B, 128, 128, 64, 64, 216, 0);
    dcn(f1l1, gOM, gSP, dw+2*DWS, db+2*DBS, gA, B, 128, 128, 0);
    up2(gL2f, gUP, B, 64, 64, 64, 1.0f);
    conv3(gA, gUP, w128+6*W128S, b128+6*B128S, gD,  B, 128, 128, 128, 64, 64, 0);

    // ---- Cascading ----
    conv3(gD, f2l1, w128+7*W128S, b128+7*B128S, gA, B, 128, 128, 128, 64, 64, 1);
    conv3(gA, nullptr, w64+3*W64S, b64+3*B64S, gB, B, 128, 128, 64, 64, 64, 1);
    conv3(gB, nullptr, om_w+3*OMWS, om_b+3*OMBS, gOM, B, 128, 128, 64, 64, 216, 0);
    dcn(gD, gOM, gSP, dw+3*DWS, db+3*DBS, outp, B, 128, 128, 1);
}

// round 5
// speedup vs baseline: 1.0840x; 1.0312x over previous
#include <cuda_runtime.h>
#include <cuda_bf16.h>
#include <cstddef>
#include <math.h>

// ---------------------------------------------------------------------------
// PCDAlign fp32, scalar-FFMA issue-optimized.
//   conv3s_k<TW> : 3x3 conv pad1. 1024-px tile, 256 thr, 4 px/thread,
//                  8 out-ch/block, ci-chunks of 8 in smem, LDS.128 reads.
//   up2_k        : bilinear 2x upsample * scale.
//   dcn_sample_k : modulated deformable bilinear sampling -> samp[b][576][HW]
//   gemm576s_k   : out[64,HW] = W[64,576] @ samp (+bias, opt lrelu).
// ---------------------------------------------------------------------------

#define NF 64
#define CO_BLK 8

// scratch (B=4 fixed)
#define L1N (4*64*128*128)
#define L2N (4*64*64*64)
#define L3N (4*64*32*32)
#define OMN (4*216*128*128)
#define SAMPN (4*576*128*128)

__device__ float g_A [L1N];
__device__ float g_B [L1N];
__device__ float g_C [L1N];
__device__ float g_D [L1N];
__device__ float g_UP[L1N];
__device__ float g_OM[OMN];
__device__ float g_SAMP[SAMPN];
__device__ float g_L3o[L3N];
__device__ float g_L3f[L3N];
__device__ float g_L2o[L2N];
__device__ float g_L2f[L2N];

// ---------------------------------------------------------------------------
// conv3s: TW x (1024/TW) pixel tile, 256 threads, 4 px/thread, 8 co/block.
// ---------------------------------------------------------------------------
template<int TW>
__global__ __launch_bounds__(256, 2)
void conv3s_k(const float* __restrict__ in1, const float* __restrict__ in2,
              const float* __restrict__ wt,  const float* __restrict__ bs,
              float* __restrict__ out,
              int H, int W, int Cin, int C1, int Cout, int act)
{
    constexpr int TH = 1024 / TW;
    constexpr int PR = TH + 2;
    constexpr int PC = TW + 2;
    constexpr int PS = TW + 8;          // row stride; cols PC..PS-1 unused
    const int tilesX = W / TW;
    const int tx0 = (blockIdx.x % tilesX) * TW;
    const int ty0 = (blockIdx.x / tilesX) * TH;
    const int b   = blockIdx.y;
    const int co0 = blockIdx.z * CO_BLK;
    const int tid = threadIdx.x;
    const int px0 = (tid % (TW/4)) * 4;
    const int py  = tid / (TW/4);
    const int HW  = H * W;
    const int C2  = Cin - C1;

    __shared__ float sIn[8][PR*PS];
    __shared__ float sW [CO_BLK*8*12];     // [co][ci][12], 9 used, f4-aligned

    float acc[CO_BLK][4];
#pragma unroll
    for (int i = 0; i < CO_BLK; i++)
#pragma unroll
        for (int j = 0; j < 4; j++) acc[i][j] = 0.f;

    for (int c0 = 0; c0 < Cin; c0 += 8) {
        __syncthreads();
        // input patches PRxPC (zero-padded at borders)
        for (int idx = tid; idx < 8*PR*PC; idx += 256) {
            int ci = idx / (PR*PC);
            int r  = idx - ci*(PR*PC);
            int pr = r / PC, pc = r - pr*PC;
            int gy = ty0 - 1 + pr, gx = tx0 - 1 + pc;
            float v = 0.f;
            if ((unsigned)gy < (unsigned)H && (unsigned)gx < (unsigned)W) {
                int c = c0 + ci;
                const float* src = (c < C1)
                    ? in1 + ((size_t)b*C1 + c     ) * HW
                    : in2 + ((size_t)b*C2 + (c-C1)) * HW;
                v = src[gy*W + gx];
            }
            sIn[ci][pr*PS + pc] = v;
        }
        // weights
        for (int idx = tid; idx < CO_BLK*8*9; idx += 256) {
            int co = idx / 72, r = idx - co*72;
            int ci = r / 9,    k = r - ci*9;
            sW[co*96 + ci*12 + k] = wt[((size_t)(co0+co)*Cin + (c0+ci))*9 + k];
        }
        __syncthreads();

#pragma unroll
        for (int ci = 0; ci < 8; ci++) {
            float s[3][8];
#pragma unroll
            for (int r = 0; r < 3; r++) {
                float4 a = *reinterpret_cast<const float4*>(&sIn[ci][(py+r)*PS + px0]);
                float4 bq = *reinterpret_cast<const float4*>(&sIn[ci][(py+r)*PS + px0 + 4]);
                s[r][0]=a.x; s[r][1]=a.y; s[r][2]=a.z; s[r][3]=a.w;
                s[r][4]=bq.x; s[r][5]=bq.y; s[r][6]=bq.z; s[r][7]=bq.w;
            }
#pragma unroll
            for (int co = 0; co < CO_BLK; co++) {
                const float4* wp = reinterpret_cast<const float4*>(&sW[co*96 + ci*12]);
                float4 w0 = wp[0], w1 = wp[1], w2 = wp[2];
                float wk[9] = {w0.x,w0.y,w0.z,w0.w,w1.x,w1.y,w1.z,w1.w,w2.x};
#pragma unroll
                for (int j = 0; j < 4; j++) {
                    float a = acc[co][j];
                    a += wk[0]*s[0][j]   + wk[1]*s[0][j+1] + wk[2]*s[0][j+2];
                    a += wk[3]*s[1][j]   + wk[4]*s[1][j+1] + wk[5]*s[1][j+2];
                    a += wk[6]*s[2][j]   + wk[7]*s[2][j+1] + wk[8]*s[2][j+2];
                    acc[co][j] = a;
                }
            }
        }
    }

    const int y = ty0 + py, x = tx0 + px0;
#pragma unroll
    for (int co = 0; co < CO_BLK; co++) {
        float bv = __ldg(bs + co0 + co);
        float v0 = acc[co][0] + bv, v1 = acc[co][1] + bv;
        float v2 = acc[co][2] + bv, v3 = acc[co][3] + bv;
        if (act) {
            v0 = v0 >= 0.f ? v0 : 0.1f*v0;
            v1 = v1 >= 0.f ? v1 : 0.1f*v1;
            v2 = v2 >= 0.f ? v2 : 0.1f*v2;
            v3 = v3 >= 0.f ? v3 : 0.1f*v3;
        }
        size_t base = (((size_t)b*Cout + co0 + co)*H + y)*W + x;
        *reinterpret_cast<float4*>(out + base) = make_float4(v0, v1, v2, v3);
    }
}

// ---------------------------------------------------------------------------
// bilinear 2x upsample (align_corners=False), * scale
// ---------------------------------------------------------------------------
__global__ void up2_k(const float* __restrict__ in, float* __restrict__ out,
                      int NC, int H, int W, float scale)
{
    const int W2 = 2*W, H2 = 2*H;
    size_t idx = (size_t)blockIdx.x * blockDim.x + threadIdx.x;
    size_t total = (size_t)NC * H2 * W2;
    if (idx >= total) return;
    int x2 = (int)(idx % W2);
    int y2 = (int)((idx / W2) % H2);
    int c  = (int)(idx / ((size_t)W2 * H2));

    float sy = (y2 + 0.5f)*0.5f - 0.5f;
    float sx = (x2 + 0.5f)*0.5f - 0.5f;
    float fy = floorf(sy), fx = floorf(sx);
    float wy = sy - fy,    wx = sx - fx;
    int y0 = (int)fy, x0 = (int)fx;
    int y0c = min(max(y0, 0), H-1), y1c = min(max(y0+1, 0), H-1);
    int x0c = min(max(x0, 0), W-1), x1c = min(max(x0+1, 0), W-1);

    const float* img = in + (size_t)c*H*W;
    float v00 = img[y0c*W + x0c];
    float v01 = img[y0c*W + x1c];
    float v10 = img[y1c*W + x0c];
    float v11 = img[y1c*W + x1c];
    float v = (1.f-wy)*((1.f-wx)*v00 + wx*v01) + wy*((1.f-wx)*v10 + wx*v11);
    out[idx] = v * scale;
}

// ---------------------------------------------------------------------------
// DCN stage 1: modulated deformable bilinear sampling (unchanged, proven).
// ---------------------------------------------------------------------------
__global__ __launch_bounds__(256)
void dcn_sample_k(const float* __restrict__ x, const float* __restrict__ om,
                  float* __restrict__ samp, int H, int W)
{
    const int HW = H * W;
    const int px = blockIdx.x * 256 + threadIdx.x;
    const int gk = blockIdx.y;
    const int b  = blockIdx.z;
    const int g  = gk / 9, k = gk - g*9;

    const float* omb = om + (size_t)b*216*HW + px;
    float oy = __ldg(omb + (size_t)gk       *HW);
    float ox = __ldg(omb + (size_t)(72 +gk) *HW);
    float mk = __ldg(omb + (size_t)(144+gk) *HW);
    mk = 1.f / (1.f + expf(-mk));

    const int hr = px / W, wc = px - hr*W;
    float py = oy + (float)(k/3 - 1) + (float)hr;
    float pv = ox + (float)(k%3 - 1) + (float)wc;
    float fy = floorf(py), fx = floorf(pv);
    float wy = py - fy,    wx = pv - fx;
    int y0 = (int)fy, x0 = (int)fx;
    int y1 = y0 + 1,  x1 = x0 + 1;
    float vy0 = (y0 >= 0 && y0 < H) ? 1.f : 0.f;
    float vy1 = (y1 >= 0 && y1 < H) ? 1.f : 0.f;
    float vx0 = (x0 >= 0 && x0 < W) ? 1.f : 0.f;
    float vx1 = (x1 >= 0 && x1 < W) ? 1.f : 0.f;
    float b00 = mk * (1.f-wy)*(1.f-wx) * vy0*vx0;
    float b01 = mk * (1.f-wy)*wx       * vy0*vx1;
    float b10 = mk * wy*(1.f-wx)       * vy1*vx0;
    float b11 = mk * wy*wx             * vy1*vx1;
    int cy0 = min(max(y0,0),H-1), cy1 = min(max(y1,0),H-1);
    int cx0 = min(max(x0,0),W-1), cx1 = min(max(x1,0),W-1);
    int o00 = cy0*W + cx0, o01 = cy0*W + cx1;
    int o10 = cy1*W + cx0, o11 = cy1*W + cx1;

    const float* xg = x + ((size_t)b*64 + g*8)*HW;
    float* sp = samp + ((size_t)b*576 + (size_t)(g*8)*9 + k)*HW + px;
#pragma unroll
    for (int cc = 0; cc < 8; cc++) {
        const float* img = xg + (size_t)cc*HW;
        float v = b00*__ldg(img+o00) + b01*__ldg(img+o01)
                + b10*__ldg(img+o10) + b11*__ldg(img+o11);
        sp[(size_t)cc*9*HW] = v;
    }
}

// ---------------------------------------------------------------------------
// DCN stage 2: out[b,64,HW] = W[64,576] @ samp[b,576,HW] + bias (opt lrelu)
// 256 threads, 1024-px tile, 16 co/block, scalar FMA.
// ---------------------------------------------------------------------------
__global__ __launch_bounds__(256, 2)
void gemm576s_k(const float* __restrict__ samp, const float* __restrict__ wt,
                const float* __restrict__ bs, float* __restrict__ out,
                int HW, int act)
{
    const int tid = threadIdx.x;
    const int b   = blockIdx.y;
    const int co0 = blockIdx.z * 16;
    const int pxb = blockIdx.x * 1024;

    __shared__ float sS[4][1024];
    __shared__ float sW[16][4];

    float4 acc[16];
#pragma unroll
    for (int i = 0; i < 16; i++) acc[i] = make_float4(0.f,0.f,0.f,0.f);

    const float* sb = samp + (size_t)b*576*HW + pxb;

    for (int k0 = 0; k0 < 576; k0 += 4) {
        __syncthreads();
#pragma unroll
        for (int r = 0; r < 4; r++) {
            const float4* src = reinterpret_cast<const float4*>(sb + (size_t)(k0+r)*HW);
            reinterpret_cast<float4*>(sS[r])[tid] = src[tid];
        }
        if (tid < 64) {
            int co = tid >> 2, k = tid & 3;
            sW[co][k] = __ldg(wt + (size_t)(co0+co)*576 + k0 + k);
        }
        __syncthreads();

        float4 sr[4];
#pragma unroll
        for (int r = 0; r < 4; r++)
            sr[r] = reinterpret_cast<const float4*>(sS[r])[tid];

#pragma unroll
        for (int co = 0; co < 16; co++) {
            float4 wv = *reinterpret_cast<const float4*>(&sW[co][0]);
            float4 a = acc[co];
            a.x += wv.x*sr[0].x + wv.y*sr[1].x + wv.z*sr[2].x + wv.w*sr[3].x;
            a.y += wv.x*sr[0].y + wv.y*sr[1].y + wv.z*sr[2].y + wv.w*sr[3].y;
            a.z += wv.x*sr[0].z + wv.y*sr[1].z + wv.z*sr[2].z + wv.w*sr[3].z;
            a.w += wv.x*sr[0].w + wv.y*sr[1].w + wv.z*sr[2].w + wv.w*sr[3].w;
            acc[co] = a;
        }
    }

    const int px = pxb + tid*4;
#pragma unroll
    for (int co = 0; co < 16; co++) {
        float bv = __ldg(bs + co0 + co);
        float v0 = acc[co].x + bv, v1 = acc[co].y + bv;
        float v2 = acc[co].z + bv, v3 = acc[co].w + bv;
        if (act) {
            v0 = v0 >= 0.f ? v0 : 0.1f*v0;
            v1 = v1 >= 0.f ? v1 : 0.1f*v1;
            v2 = v2 >= 0.f ? v2 : 0.1f*v2;
            v3 = v3 >= 0.f ? v3 : 0.1f*v3;
        }
        *reinterpret_cast<float4*>(out + ((size_t)b*64 + co0 + co)*HW + px)
            = make_float4(v0, v1, v2, v3);
    }
}

// ---------------------------------------------------------------------------
// host orchestration
// ---------------------------------------------------------------------------
static void conv3(const float* i1, const float* i2, const float* w, const float* b_,
                  float* o, int B, int H, int W, int Cin, int C1, int Cout, int act)
{
    dim3 blk(256);
    if (W >= 64) {
        dim3 grid((W/64)*(H/16), B, Cout/CO_BLK);
        conv3s_k<64><<<grid, blk>>>(i1, i2, w, b_, o, H, W, Cin, C1, Cout, act);
    } else {
        dim3 grid((W/32)*(H/32), B, Cout/CO_BLK);
        conv3s_k<32><<<grid, blk>>>(i1, i2, w, b_, o, H, W, Cin, C1, Cout, act);
    }
}

static void up2(const float* in, float* out, int B, int C, int H, int W, float scale)
{
    size_t n = (size_t)B*C*2*H*2*W;
    int blocks = (int)((n + 255) / 256);
    up2_k<<<blocks, 256>>>(in, out, B*C, H, W, scale);
}

static void dcn(const float* x, const float* om, float* sampbuf,
                const float* w, const float* b_,
                float* out, int B, int H, int W, int act)
{
    int HW = H*W;
    dim3 sg(HW/256, 72, B);
    dcn_sample_k<<<sg, 256>>>(x, om, sampbuf, H, W);
    dim3 gg(HW/1024, B, 4);
    gemm576s_k<<<gg, 256>>>(sampbuf, w, b_, out, HW, act);
}

extern "C" void kernel_launch(void* const* d_in, const int* in_sizes, int n_in,
                              void* d_out, int out_size)
{
    const float* f1l1 = (const float*)d_in[0];
    const float* f1l2 = (const float*)d_in[1];
    const float* f1l3 = (const float*)d_in[2];
    const float* f2l1 = (const float*)d_in[3];
    const float* f2l2 = (const float*)d_in[4];
    const float* f2l3 = (const float*)d_in[5];
    const float* w128 = (const float*)d_in[6];
    const float* b128 = (const float*)d_in[7];
    const float* w64  = (const float*)d_in[8];
    const float* b64  = (const float*)d_in[9];
    const float* om_w = (const float*)d_in[10];
    const float* om_b = (const float*)d_in[11];
    const float* dw   = (const float*)d_in[12];
    const float* db   = (const float*)d_in[13];
    float* outp = (float*)d_out;

    const int B = in_sizes[0] / (NF*128*128);   // 4

    float *gA,*gB,*gC,*gD,*gUP,*gOM,*gSP,*gL3o,*gL3f,*gL2o,*gL2f;
    cudaGetSymbolAddress((void**)&gA,  g_A);
    cudaGetSymbolAddress((void**)&gB,  g_B);
    cudaGetSymbolAddress((void**)&gC,  g_C);
    cudaGetSymbolAddress((void**)&gD,  g_D);
    cudaGetSymbolAddress((void**)&gUP, g_UP);
    cudaGetSymbolAddress((void**)&gOM, g_OM);
    cudaGetSymbolAddress((void**)&gSP, g_SAMP);
    cudaGetSymbolAddress((void**)&gL3o, g_L3o);
    cudaGetSymbolAddress((void**)&gL3f, g_L3f);
    cudaGetSymbolAddress((void**)&gL2o, g_L2o);
    cudaGetSymbolAddress((void**)&gL2f, g_L2f);

    const size_t W128S = (size_t)64*128*9, B128S = 64;
    const size_t W64S  = (size_t)64*64*9,  B64S  = 64;
    const size_t OMWS  = (size_t)216*64*9, OMBS  = 216;
    const size_t DWS   = (size_t)64*64*9,  DBS   = 64;

    // ---- L3 (32x32) ----
    conv3(f1l3, f2l3, w128+0*W128S, b128+0*B128S, gA,  B, 32, 32, 128, 64, 64, 1);
    conv3(gA, nullptr, w64+0*W64S,  b64+0*B64S,   gL3o,B, 32, 32,  64, 64, 64, 1);
    conv3(gL3o, nullptr, om_w+0*OMWS, om_b+0*OMBS, gOM, B, 32, 32, 64, 64, 216, 0);
    dcn(f1l3, gOM, gSP, dw+0*DWS, db+0*DBS, gL3f, B, 32, 32, 1);

    // ---- L2 (64x64) ----
    conv3(f1l2, f2l2, w128+1*W128S, b128+1*B128S, gA,  B, 64, 64, 128, 64, 64, 1);
    up2(gL3o, gUP, B, 64, 32, 32, 2.0f);
    conv3(gA, gUP, w128+2*W128S, b128+2*B128S, gB,  B, 64, 64, 128, 64, 64, 1);
    conv3(gB, nullptr, w64+1*W64S, b64+1*B64S, gL2o, B, 64, 64, 64, 64, 64, 1);
    conv3(gL2o, nullptr, om_w+1*OMWS, om_b+1*OMBS, gOM, B, 64, 64, 64, 64, 216, 0);
    dcn(f1l2, gOM, gSP, dw+1*DWS, db+1*DBS, gA, B, 64, 64, 0);
    up2(gL3f, gUP, B, 64, 32, 32, 1.0f);
    conv3(gA, gUP, w128+3*W128S, b128+3*B128S, gL2f, B, 64, 64, 128, 64, 64, 1);

    // ---- L1 (128x128) ----
    conv3(f1l1, f2l1, w128+4*W128S, b128+4*B128S, gA,  B, 128, 128, 128, 64, 64, 1);
    up2(gL2o, gUP, B, 64, 64, 64, 2.0f);
    conv3(gA, gUP, w128+5*W128S, b128+5*B128S, gB,  B, 128, 128, 128, 64, 64, 1);
    conv3(gB, nullptr, w64+2*W64S, b64+2*B64S, gC,  B, 128, 128, 64, 64, 64, 1);
    conv3(gC, nullptr, om_w+2*OMWS, om_b+2*OMBS, gOM, B, 128, 128, 64, 64, 216, 0);
    dcn(f1l1, gOM, gSP, dw+2*DWS, db+2*DBS, gA, B, 128, 128, 0);
    up2(gL2f, gUP, B, 64, 64, 64, 1.0f);
    conv3(gA, gUP, w128+6*W128S, b128+6*B128S, gD,  B, 128, 128, 128, 64, 64, 0);

    // ---- Cascading ----
    conv3(gD, f2l1, w128+7*W128S, b128+7*B128S, gA, B, 128, 128, 128, 64, 64, 1);
    conv3(gA, nullptr, w64+3*W64S, b64+3*B64S, gB, B, 128, 128, 64, 64, 64, 1);
    conv3(gB, nullptr, om_w+3*OMWS, om_b+3*OMBS, gOM, B, 128, 128, 64, 64, 216, 0);
    dcn(gD, gOM, gSP, dw+3*DWS, db+3*DBS, outp, B, 128, 128, 1);
}

// round 6
// speedup vs baseline: 1.2936x; 1.1933x over previous
#include <cuda_runtime.h>
#include <cuda_bf16.h>
#include <cstddef>
#include <math.h>

// ---------------------------------------------------------------------------
// PCDAlign fp32, scalar FFMA, structural fixes:
//  conv_big_k<CB> : 64x16 px tile, 4 px/thread, CB out-ch/block (8 or 16).
//  conv_sm_k<CB>  : 32x8 px tile, 1 px/thread (small levels, high occupancy).
//  up2_k          : bilinear 2x upsample * scale.
//  dcn_sample_k   : deformable bilinear sampling -> samp[b][576][HW].
//  gemm576s_k     : 1024-px tile GEMM (L1);  gemm576sm_k : 256-px tile (L2/L3).
// ---------------------------------------------------------------------------

#define NF 64

// scratch (B=4 fixed)
#define L1N (4*64*128*128)
#define L2N (4*64*64*64)
#define L3N (4*64*32*32)
#define OMN (4*216*128*128)
#define SAMPN (4*576*128*128)

__device__ float g_A [L1N];
__device__ float g_B [L1N];
__device__ float g_C [L1N];
__device__ float g_D [L1N];
__device__ float g_UP[L1N];
__device__ float g_OM[OMN];
__device__ float g_SAMP[SAMPN];
__device__ float g_L3o[L3N];
__device__ float g_L3f[L3N];
__device__ float g_L2o[L2N];
__device__ float g_L2f[L2N];

// ---------------------------------------------------------------------------
// conv_big: 64x16 pixel tile, 256 threads, 4 px/thread, CB out-ch/block.
// ci-chunks of 8 via smem. Weights padded to 12 floats (float4 reads).
// ---------------------------------------------------------------------------
template<int CB>
__global__ __launch_bounds__(256, 2)
void conv_big_k(const float* __restrict__ in1, const float* __restrict__ in2,
                const float* __restrict__ wt,  const float* __restrict__ bs,
                float* __restrict__ out,
                int H, int W, int Cin, int C1, int Cout, int act)
{
    constexpr int TW = 64, TH = 16;
    constexpr int PR = TH + 2, PC = TW + 2, PS = TW + 8;
    const int tilesX = W / TW;
    const int tx0 = (blockIdx.x % tilesX) * TW;
    const int ty0 = (blockIdx.x / tilesX) * TH;
    const int b   = blockIdx.y;
    const int co0 = blockIdx.z * CB;
    const int tid = threadIdx.x;
    const int px0 = (tid % (TW/4)) * 4;
    const int py  = tid / (TW/4);
    const int HW  = H * W;
    const int C2  = Cin - C1;

    __shared__ float sIn[8][PR*PS];
    __shared__ float sW [CB*8*12];

    float acc[CB][4];
#pragma unroll
    for (int i = 0; i < CB; i++)
#pragma unroll
        for (int j = 0; j < 4; j++) acc[i][j] = 0.f;

    for (int c0 = 0; c0 < Cin; c0 += 8) {
        __syncthreads();
        for (int idx = tid; idx < 8*PR*PC; idx += 256) {
            int ci = idx / (PR*PC);
            int r  = idx - ci*(PR*PC);
            int pr = r / PC, pc = r - pr*PC;
            int gy = ty0 - 1 + pr, gx = tx0 - 1 + pc;
            float v = 0.f;
            if ((unsigned)gy < (unsigned)H && (unsigned)gx < (unsigned)W) {
                int c = c0 + ci;
                const float* src = (c < C1)
                    ? in1 + ((size_t)b*C1 + c     ) * HW
                    : in2 + ((size_t)b*C2 + (c-C1)) * HW;
                v = src[gy*W + gx];
            }
            sIn[ci][pr*PS + pc] = v;
        }
        for (int idx = tid; idx < CB*8*9; idx += 256) {
            int co = idx / 72, r = idx - co*72;
            int ci = r / 9,    k = r - ci*9;
            sW[co*96 + ci*12 + k] = wt[((size_t)(co0+co)*Cin + (c0+ci))*9 + k];
        }
        __syncthreads();

#pragma unroll
        for (int ci = 0; ci < 8; ci++) {
            float s[3][8];
#pragma unroll
            for (int r = 0; r < 3; r++) {
                float4 a = *reinterpret_cast<const float4*>(&sIn[ci][(py+r)*PS + px0]);
                float4 bq = *reinterpret_cast<const float4*>(&sIn[ci][(py+r)*PS + px0 + 4]);
                s[r][0]=a.x; s[r][1]=a.y; s[r][2]=a.z; s[r][3]=a.w;
                s[r][4]=bq.x; s[r][5]=bq.y; s[r][6]=bq.z; s[r][7]=bq.w;
            }
#pragma unroll
            for (int co = 0; co < CB; co++) {
                const float4* wp = reinterpret_cast<const float4*>(&sW[co*96 + ci*12]);
                float4 w0 = wp[0], w1 = wp[1], w2 = wp[2];
                float wk[9] = {w0.x,w0.y,w0.z,w0.w,w1.x,w1.y,w1.z,w1.w,w2.x};
#pragma unroll
                for (int j = 0; j < 4; j++) {
                    float a = acc[co][j];
                    a += wk[0]*s[0][j] + wk[1]*s[0][j+1] + wk[2]*s[0][j+2];
                    a += wk[3]*s[1][j] + wk[4]*s[1][j+1] + wk[5]*s[1][j+2];
                    a += wk[6]*s[2][j] + wk[7]*s[2][j+1] + wk[8]*s[2][j+2];
                    acc[co][j] = a;
                }
            }
        }
    }

    const int y = ty0 + py, x = tx0 + px0;
#pragma unroll
    for (int co = 0; co < CB; co++) {
        float bv = __ldg(bs + co0 + co);
        float v0 = acc[co][0] + bv, v1 = acc[co][1] + bv;
        float v2 = acc[co][2] + bv, v3 = acc[co][3] + bv;
        if (act) {
            v0 = v0 >= 0.f ? v0 : 0.1f*v0;
            v1 = v1 >= 0.f ? v1 : 0.1f*v1;
            v2 = v2 >= 0.f ? v2 : 0.1f*v2;
            v3 = v3 >= 0.f ? v3 : 0.1f*v3;
        }
        size_t base = (((size_t)b*Cout + co0 + co)*H + y)*W + x;
        *reinterpret_cast<float4*>(out + base) = make_float4(v0, v1, v2, v3);
    }
}

// ---------------------------------------------------------------------------
// conv_sm: 32x8 pixel tile, 256 threads, 1 px/thread (small images).
// ---------------------------------------------------------------------------
template<int CB>
__global__ __launch_bounds__(256, 4)
void conv_sm_k(const float* __restrict__ in1, const float* __restrict__ in2,
               const float* __restrict__ wt,  const float* __restrict__ bs,
               float* __restrict__ out,
               int H, int W, int Cin, int C1, int Cout, int act)
{
    constexpr int TW = 32, TH = 8;
    constexpr int PR = TH + 2, PC = TW + 2, PS = TW + 8;
    const int tilesX = W / TW;
    const int tx0 = (blockIdx.x % tilesX) * TW;
    const int ty0 = (blockIdx.x / tilesX) * TH;
    const int b   = blockIdx.y;
    const int co0 = blockIdx.z * CB;
    const int tid = threadIdx.x;
    const int px0 = tid & 31;
    const int py  = tid >> 5;
    const int HW  = H * W;
    const int C2  = Cin - C1;

    __shared__ float sIn[8][PR*PS];
    __shared__ float sW [CB*8*12];

    float acc[CB];
#pragma unroll
    for (int i = 0; i < CB; i++) acc[i] = 0.f;

    for (int c0 = 0; c0 < Cin; c0 += 8) {
        __syncthreads();
        for (int idx = tid; idx < 8*PR*PC; idx += 256) {
            int ci = idx / (PR*PC);
            int r  = idx - ci*(PR*PC);
            int pr = r / PC, pc = r - pr*PC;
            int gy = ty0 - 1 + pr, gx = tx0 - 1 + pc;
            float v = 0.f;
            if ((unsigned)gy < (unsigned)H && (unsigned)gx < (unsigned)W) {
                int c = c0 + ci;
                const float* src = (c < C1)
                    ? in1 + ((size_t)b*C1 + c     ) * HW
                    : in2 + ((size_t)b*C2 + (c-C1)) * HW;
                v = src[gy*W + gx];
            }
            sIn[ci][pr*PS + pc] = v;
        }
        for (int idx = tid; idx < CB*8*9; idx += 256) {
            int co = idx / 72, r = idx - co*72;
            int ci = r / 9,    k = r - ci*9;
            sW[co*96 + ci*12 + k] = wt[((size_t)(co0+co)*Cin + (c0+ci))*9 + k];
        }
        __syncthreads();

#pragma unroll
        for (int ci = 0; ci < 8; ci++) {
            float s[3][3];
#pragma unroll
            for (int r = 0; r < 3; r++) {
                s[r][0] = sIn[ci][(py+r)*PS + px0 + 0];
                s[r][1] = sIn[ci][(py+r)*PS + px0 + 1];
                s[r][2] = sIn[ci][(py+r)*PS + px0 + 2];
            }
#pragma unroll
            for (int co = 0; co < CB; co++) {
                const float4* wp = reinterpret_cast<const float4*>(&sW[co*96 + ci*12]);
                float4 w0 = wp[0], w1 = wp[1], w2 = wp[2];
                float a = acc[co];
                a += w0.x*s[0][0] + w0.y*s[0][1] + w0.z*s[0][2];
                a += w0.w*s[1][0] + w1.x*s[1][1] + w1.y*s[1][2];
                a += w1.z*s[2][0] + w1.w*s[2][1] + w2.x*s[2][2];
                acc[co] = a;
            }
        }
    }

    const int y = ty0 + py, x = tx0 + px0;
#pragma unroll
    for (int co = 0; co < CB; co++) {
        float v = acc[co] + __ldg(bs + co0 + co);
        if (act) v = v >= 0.f ? v : 0.1f*v;
        out[(((size_t)b*Cout + co0 + co)*H + y)*W + x] = v;
    }
}

// ---------------------------------------------------------------------------
// bilinear 2x upsample (align_corners=False), * scale
// ---------------------------------------------------------------------------
__global__ void up2_k(const float* __restrict__ in, float* __restrict__ out,
                      int NC, int H, int W, float scale)
{
    const int W2 = 2*W, H2 = 2*H;
    size_t idx = (size_t)blockIdx.x * blockDim.x + threadIdx.x;
    size_t total = (size_t)NC * H2 * W2;
    if (idx >= total) return;
    int x2 = (int)(idx % W2);
    int y2 = (int)((idx / W2) % H2);
    int c  = (int)(idx / ((size_t)W2 * H2));

    float sy = (y2 + 0.5f)*0.5f - 0.5f;
    float sx = (x2 + 0.5f)*0.5f - 0.5f;
    float fy = floorf(sy), fx = floorf(sx);
    float wy = sy - fy,    wx = sx - fx;
    int y0 = (int)fy, x0 = (int)fx;
    int y0c = min(max(y0, 0), H-1), y1c = min(max(y0+1, 0), H-1);
    int x0c = min(max(x0, 0), W-1), x1c = min(max(x0+1, 0), W-1);

    const float* img = in + (size_t)c*H*W;
    float v00 = img[y0c*W + x0c];
    float v01 = img[y0c*W + x1c];
    float v10 = img[y1c*W + x0c];
    float v11 = img[y1c*W + x1c];
    float v = (1.f-wy)*((1.f-wx)*v00 + wx*v01) + wy*((1.f-wx)*v10 + wx*v11);
    out[idx] = v * scale;
}

// ---------------------------------------------------------------------------
// DCN stage 1: modulated deformable bilinear sampling.
// ---------------------------------------------------------------------------
__global__ __launch_bounds__(256)
void dcn_sample_k(const float* __restrict__ x, const float* __restrict__ om,
                  float* __restrict__ samp, int H, int W)
{
    const int HW = H * W;
    const int px = blockIdx.x * 256 + threadIdx.x;
    const int gk = blockIdx.y;
    const int b  = blockIdx.z;
    const int g  = gk / 9, k = gk - g*9;

    const float* omb = om + (size_t)b*216*HW + px;
    float oy = __ldg(omb + (size_t)gk       *HW);
    float ox = __ldg(omb + (size_t)(72 +gk) *HW);
    float mk = __ldg(omb + (size_t)(144+gk) *HW);
    mk = 1.f / (1.f + expf(-mk));

    const int hr = px / W, wc = px - hr*W;
    float py = oy + (float)(k/3 - 1) + (float)hr;
    float pv = ox + (float)(k%3 - 1) + (float)wc;
    float fy = floorf(py), fx = floorf(pv);
    float wy = py - fy,    wx = pv - fx;
    int y0 = (int)fy, x0 = (int)fx;
    int y1 = y0 + 1,  x1 = x0 + 1;
    float vy0 = (y0 >= 0 && y0 < H) ? 1.f : 0.f;
    float vy1 = (y1 >= 0 && y1 < H) ? 1.f : 0.f;
    float vx0 = (x0 >= 0 && x0 < W) ? 1.f : 0.f;
    float vx1 = (x1 >= 0 && x1 < W) ? 1.f : 0.f;
    float b00 = mk * (1.f-wy)*(1.f-wx) * vy0*vx0;
    float b01 = mk * (1.f-wy)*wx       * vy0*vx1;
    float b10 = mk * wy*(1.f-wx)       * vy1*vx0;
    float b11 = mk * wy*wx             * vy1*vx1;
    int cy0 = min(max(y0,0),H-1), cy1 = min(max(y1,0),H-1);
    int cx0 = min(max(x0,0),W-1), cx1 = min(max(x1,0),W-1);
    int o00 = cy0*W + cx0, o01 = cy0*W + cx1;
    int o10 = cy1*W + cx0, o11 = cy1*W + cx1;

    const float* xg = x + ((size_t)b*64 + g*8)*HW;
    float* sp = samp + ((size_t)b*576 + (size_t)(g*8)*9 + k)*HW + px;
#pragma unroll
    for (int cc = 0; cc < 8; cc++) {
        const float* img = xg + (size_t)cc*HW;
        float v = b00*__ldg(img+o00) + b01*__ldg(img+o01)
                + b10*__ldg(img+o10) + b11*__ldg(img+o11);
        sp[(size_t)cc*9*HW] = v;
    }
}

// ---------------------------------------------------------------------------
// DCN stage 2 (large): 1024-px tile, 4 px/thread, 16 co/block.
// ---------------------------------------------------------------------------
__global__ __launch_bounds__(256, 2)
void gemm576s_k(const float* __restrict__ samp, const float* __restrict__ wt,
                const float* __restrict__ bs, float* __restrict__ out,
                int HW, int act)
{
    const int tid = threadIdx.x;
    const int b   = blockIdx.y;
    const int co0 = blockIdx.z * 16;
    const int pxb = blockIdx.x * 1024;

    __shared__ float sS[4][1024];
    __shared__ float sW[16][4];

    float4 acc[16];
#pragma unroll
    for (int i = 0; i < 16; i++) acc[i] = make_float4(0.f,0.f,0.f,0.f);

    const float* sb = samp + (size_t)b*576*HW + pxb;

    for (int k0 = 0; k0 < 576; k0 += 4) {
        __syncthreads();
#pragma unroll
        for (int r = 0; r < 4; r++) {
            const float4* src = reinterpret_cast<const float4*>(sb + (size_t)(k0+r)*HW);
            reinterpret_cast<float4*>(sS[r])[tid] = src[tid];
        }
        if (tid < 64) {
            int co = tid >> 2, k = tid & 3;
            sW[co][k] = __ldg(wt + (size_t)(co0+co)*576 + k0 + k);
        }
        __syncthreads();

        float4 sr[4];
#pragma unroll
        for (int r = 0; r < 4; r++)
            sr[r] = reinterpret_cast<const float4*>(sS[r])[tid];

#pragma unroll
        for (int co = 0; co < 16; co++) {
            float4 wv = *reinterpret_cast<const float4*>(&sW[co][0]);
            float4 a = acc[co];
            a.x += wv.x*sr[0].x + wv.y*sr[1].x + wv.z*sr[2].x + wv.w*sr[3].x;
            a.y += wv.x*sr[0].y + wv.y*sr[1].y + wv.z*sr[2].y + wv.w*sr[3].y;
            a.z += wv.x*sr[0].z + wv.y*sr[1].z + wv.z*sr[2].z + wv.w*sr[3].z;
            a.w += wv.x*sr[0].w + wv.y*sr[1].w + wv.z*sr[2].w + wv.w*sr[3].w;
            acc[co] = a;
        }
    }

    const int px = pxb + tid*4;
#pragma unroll
    for (int co = 0; co < 16; co++) {
        float bv = __ldg(bs + co0 + co);
        float v0 = acc[co].x + bv, v1 = acc[co].y + bv;
        float v2 = acc[co].z + bv, v3 = acc[co].w + bv;
        if (act) {
            v0 = v0 >= 0.f ? v0 : 0.1f*v0;
            v1 = v1 >= 0.f ? v1 : 0.1f*v1;
            v2 = v2 >= 0.f ? v2 : 0.1f*v2;
            v3 = v3 >= 0.f ? v3 : 0.1f*v3;
        }
        *reinterpret_cast<float4*>(out + ((size_t)b*64 + co0 + co)*HW + px)
            = make_float4(v0, v1, v2, v3);
    }
}

// ---------------------------------------------------------------------------
// DCN stage 2 (small): 256-px tile, 1 px/thread, 16 co/block.
// ---------------------------------------------------------------------------
__global__ __launch_bounds__(256, 4)
void gemm576sm_k(const float* __restrict__ samp, const float* __restrict__ wt,
                 const float* __restrict__ bs, float* __restrict__ out,
                 int HW, int act)
{
    const int tid = threadIdx.x;
    const int b   = blockIdx.y;
    const int co0 = blockIdx.z * 16;
    const int pxb = blockIdx.x * 256;

    __shared__ float sS[4][256];
    __shared__ float sW[16][4];

    float acc[16];
#pragma unroll
    for (int i = 0; i < 16; i++) acc[i] = 0.f;

    const float* sb = samp + (size_t)b*576*HW + pxb;

    for (int k0 = 0; k0 < 576; k0 += 4) {
        __syncthreads();
#pragma unroll
        for (int r = 0; r < 4; r++)
            sS[r][tid] = sb[(size_t)(k0+r)*HW + tid];
        if (tid < 64) {
            int co = tid >> 2, k = tid & 3;
            sW[co][k] = __ldg(wt + (size_t)(co0+co)*576 + k0 + k);
        }
        __syncthreads();

        float s0 = sS[0][tid], s1 = sS[1][tid], s2 = sS[2][tid], s3 = sS[3][tid];
#pragma unroll
        for (int co = 0; co < 16; co++) {
            float4 wv = *reinterpret_cast<const float4*>(&sW[co][0]);
            acc[co] += wv.x*s0 + wv.y*s1 + wv.z*s2 + wv.w*s3;
        }
    }

    const int px = pxb + tid;
#pragma unroll
    for (int co = 0; co < 16; co++) {
        float v = acc[co] + __ldg(bs + co0 + co);
        if (act) v = v >= 0.f ? v : 0.1f*v;
        out[((size_t)b*64 + co0 + co)*HW + px] = v;
    }
}

// ---------------------------------------------------------------------------
// host orchestration
// ---------------------------------------------------------------------------
static void conv3(const float* i1, const float* i2, const float* w, const float* b_,
                  float* o, int B, int H, int W, int Cin, int C1, int Cout, int act)
{
    dim3 blk(256);
    if (W >= 64) {
        if (Cout == 64 && W == 128) {
            dim3 grid((W/64)*(H/16), B, 4);
            conv_big_k<16><<<grid, blk>>>(i1, i2, w, b_, o, H, W, Cin, C1, Cout, act);
        } else {
            dim3 grid((W/64)*(H/16), B, Cout/8);
            conv_big_k<8><<<grid, blk>>>(i1, i2, w, b_, o, H, W, Cin, C1, Cout, act);
        }
    } else {
        dim3 grid((W/32)*(H/8), B, Cout/8);
        conv_sm_k<8><<<grid, blk>>>(i1, i2, w, b_, o, H, W, Cin, C1, Cout, act);
    }
}

static void up2(const float* in, float* out, int B, int C, int H, int W, float scale)
{
    size_t n = (size_t)B*C*2*H*2*W;
    int blocks = (int)((n + 255) / 256);
    up2_k<<<blocks, 256>>>(in, out, B*C, H, W, scale);
}

static void dcn(const float* x, const float* om, float* sampbuf,
                const float* w, const float* b_,
                float* out, int B, int H, int W, int act)
{
    int HW = H*W;
    dim3 sg(HW/256, 72, B);
    dcn_sample_k<<<sg, 256>>>(x, om, sampbuf, H, W);
    if (HW >= 16384) {
        dim3 gg(HW/1024, B, 4);
        gemm576s_k<<<gg, 256>>>(sampbuf, w, b_, out, HW, act);
    } else {
        dim3 gg(HW/256, B, 4);
        gemm576sm_k<<<gg, 256>>>(sampbuf, w, b_, out, HW, act);
    }
}

extern "C" void kernel_launch(void* const* d_in, const int* in_sizes, int n_in,
                              void* d_out, int out_size)
{
    const float* f1l1 = (const float*)d_in[0];
    const float* f1l2 = (const float*)d_in[1];
    const float* f1l3 = (const float*)d_in[2];
    const float* f2l1 = (const float*)d_in[3];
    const float* f2l2 = (const float*)d_in[4];
    const float* f2l3 = (const float*)d_in[5];
    const float* w128 = (const float*)d_in[6];
    const float* b128 = (const float*)d_in[7];
    const float* w64  = (const float*)d_in[8];
    const float* b64  = (const float*)d_in[9];
    const float* om_w = (const float*)d_in[10];
    const float* om_b = (const float*)d_in[11];
    const float* dw   = (const float*)d_in[12];
    const float* db   = (const float*)d_in[13];
    float* outp = (float*)d_out;

    const int B = in_sizes[0] / (NF*128*128);   // 4

    float *gA,*gB,*gC,*gD,*gUP,*gOM,*gSP,*gL3o,*gL3f,*gL2o,*gL2f;
    cudaGetSymbolAddress((void**)&gA,  g_A);
    cudaGetSymbolAddress((void**)&gB,  g_B);
    cudaGetSymbolAddress((void**)&gC,  g_C);
    cudaGetSymbolAddress((void**)&gD,  g_D);
    cudaGetSymbolAddress((void**)&gUP, g_UP);
    cudaGetSymbolAddress((void**)&gOM, g_OM);
    cudaGetSymbolAddress((void**)&gSP, g_SAMP);
    cudaGetSymbolAddress((void**)&gL3o, g_L3o);
    cudaGetSymbolAddress((void**)&gL3f, g_L3f);
    cudaGetSymbolAddress((void**)&gL2o, g_L2o);
    cudaGetSymbolAddress((void**)&gL2f, g_L2f);

    const size_t W128S = (size_t)64*128*9, B128S = 64;
    const size_t W64S  = (size_t)64*64*9,  B64S  = 64;
    const size_t OMWS  = (size_t)216*64*9, OMBS  = 216;
    const size_t DWS   = (size_t)64*64*9,  DBS   = 64;

    // ---- L3 (32x32) ----
    conv3(f1l3, f2l3, w128+0*W128S, b128+0*B128S, gA,  B, 32, 32, 128, 64, 64, 1);
    conv3(gA, nullptr, w64+0*W64S,  b64+0*B64S,   gL3o,B, 32, 32,  64, 64, 64, 1);
    conv3(gL3o, nullptr, om_w+0*OMWS, om_b+0*OMBS, gOM, B, 32, 32, 64, 64, 216, 0);
    dcn(f1l3, gOM, gSP, dw+0*DWS, db+0*DBS, gL3f, B, 32, 32, 1);

    // ---- L2 (64x64) ----
    conv3(f1l2, f2l2, w128+1*W128S, b128+1*B128S, gA,  B, 64, 64, 128, 64, 64, 1);
    up2(gL3o, gUP, B, 64, 32, 32, 2.0f);
    conv3(gA, gUP, w128+2*W128S, b128+2*B128S, gB,  B, 64, 64, 128, 64, 64, 1);
    conv3(gB, nullptr, w64+1*W64S, b64+1*B64S, gL2o, B, 64, 64, 64, 64, 64, 1);
    conv3(gL2o, nullptr, om_w+1*OMWS, om_b+1*OMBS, gOM, B, 64, 64, 64, 64, 216, 0);
    dcn(f1l2, gOM, gSP, dw+1*DWS, db+1*DBS, gA, B, 64, 64, 0);
    up2(gL3f, gUP, B, 64, 32, 32, 1.0f);
    conv3(gA, gUP, w128+3*W128S, b128+3*B128S, gL2f, B, 64, 64, 128, 64, 64, 1);

    // ---- L1 (128x128) ----
    conv3(f1l1, f2l1, w128+4*W128S, b128+4*B128S, gA,  B, 128, 128, 128, 64, 64, 1);
    up2(gL2o, gUP, B, 64, 64, 64, 2.0f);
    conv3(gA, gUP, w128+5*W128S, b128+5*B128S, gB,  B, 128, 128, 128, 64, 64, 1);
    conv3(gB, nullptr, w64+2*W64S, b64+2*B64S, gC,  B, 128, 128, 64, 64, 64, 1);
    conv3(gC, nullptr, om_w+2*OMWS, om_b+2*OMBS, gOM, B, 128, 128, 64, 64, 216, 0);
    dcn(f1l1, gOM, gSP, dw+2*DWS, db+2*DBS, gA, B, 128, 128, 0);
    up2(gL2f, gUP, B, 64, 64, 64, 1.0f);
    conv3(gA, gUP, w128+6*W128S, b128+6*B128S, gD,  B, 128, 128, 128, 64, 64, 0);

    // ---- Cascading ----
    conv3(gD, f2l1, w128+7*W128S, b128+7*B128S, gA, B, 128, 128, 128, 64, 64, 1);
    conv3(gA, nullptr, w64+3*W64S, b64+3*B64S, gB, B, 128, 128, 64, 64, 64, 1);
    conv3(gB, nullptr, om_w+3*OMWS, om_b+3*OMBS, gOM, B, 128, 128, 64, 64, 216, 0);
    dcn(gD, gOM, gSP, dw+3*DWS, db+3*DBS, outp, B, 128, 128, 1);
}

// round 8
// speedup vs baseline: 2.8300x; 2.1878x over previous
#include <cuda_runtime.h>
#include <cuda_bf16.h>
#include <cstddef>
#include <cstdint>
#include <math.h>

// ---------------------------------------------------------------------------
// PCDAlign via warp-level mma.sync (bf16 hi/lo split, fp32 accum), sm_103.
//   pad_k        : concat + zero-pad [B,C,H,W] -> [B,C,H+2,W+2]
//   prep_w_k     : fp32 weights -> bf16 hi/lo, layout [set][stage][co][64]
//   mma_gemm_k   : D[128px, 64co] = A[128px, K] @ W[co, K]^T  (+bias, lrelu)
//                  per CTA; K staged 64 at a time; 8 warps, m16n8k16 HMMA.
//   up2_k        : bilinear 2x upsample * scale
//   dcn_sample_k : deformable bilinear sampling -> samp[b][576][HW]
// ---------------------------------------------------------------------------

#define NF 64

// ---------------- scratch (B=4 fixed) ----------------
#define L1N (4*64*128*128)
#define L2N (4*64*64*64)
#define L3N (4*64*32*32)
#define OMN (4*216*128*128)
#define SAMPN (4*576*128*128)
#define PADN (4*128*130*130)

__device__ float g_A [L1N];
__device__ float g_B [L1N];
__device__ float g_C [L1N];
__device__ float g_D [L1N];
__device__ float g_UP[L1N];
__device__ float g_OM[OMN];
__device__ float g_SAMP[SAMPN];
__device__ float g_PAD[PADN];
__device__ float g_L3o[L3N];
__device__ float g_L3f[L3N];
__device__ float g_L2o[L2N];
__device__ float g_L2f[L2N];

// bf16 split weights: [set][stage][co][64]
__device__ __nv_bfloat16 g_W128hi[8*18*64*64];
__device__ __nv_bfloat16 g_W128lo[8*18*64*64];
__device__ __nv_bfloat16 g_W64hi [4*9*64*64];
__device__ __nv_bfloat16 g_W64lo [4*9*64*64];
__device__ __nv_bfloat16 g_WOMhi [4*9*256*64];
__device__ __nv_bfloat16 g_WOMlo [4*9*256*64];
__device__ __nv_bfloat16 g_WDhi  [4*9*64*64];
__device__ __nv_bfloat16 g_WDlo  [4*9*64*64];

// ---------------- helpers ----------------
__device__ __forceinline__ uint32_t smem_u32(const void* p) {
    uint32_t a;
    asm("{ .reg .u64 t; cvta.to.shared.u64 t, %1; cvt.u32.u64 %0, t; }"
        : "=r"(a) : "l"(p));
    return a;
}
#define SWZ128(off) ((off) ^ (((off) >> 3) & 0x70))

__device__ __forceinline__ void ldm4(uint32_t r[4], uint32_t addr) {
    asm volatile("ldmatrix.sync.aligned.m8n8.x4.shared.b16 {%0,%1,%2,%3}, [%4];"
        : "=r"(r[0]), "=r"(r[1]), "=r"(r[2]), "=r"(r[3]) : "r"(addr));
}
__device__ __forceinline__ void mma16816(float c[4], const uint32_t a[4],
                                         uint32_t b0, uint32_t b1) {
    asm volatile(
        "mma.sync.aligned.m16n8k16.row.col.f32.bf16.bf16.f32 "
        "{%0,%1,%2,%3}, {%4,%5,%6,%7}, {%8,%9}, {%0,%1,%2,%3};"
        : "+f"(c[0]), "+f"(c[1]), "+f"(c[2]), "+f"(c[3])
        : "r"(a[0]), "r"(a[1]), "r"(a[2]), "r"(a[3]), "r"(b0), "r"(b1));
}

// ---------------------------------------------------------------------------
// pad: dst[b][c][y+1][x+1] = concat(in1,in2)[b][c][y][x], zero border
// ---------------------------------------------------------------------------
__global__ void pad_k(const float* __restrict__ in1, const float* __restrict__ in2,
                      float* __restrict__ dst, int C1, int C2, int H, int W)
{
    int Hp = H + 2, Wp = W + 2, C = C1 + C2;
    int b = blockIdx.y;
    int idx = blockIdx.x * 256 + threadIdx.x;
    if (idx >= C * Hp * Wp) return;
    int xp = idx % Wp;
    int yp = (idx / Wp) % Hp;
    int c  = idx / (Wp * Hp);
    int y = yp - 1, x = xp - 1;
    float v = 0.f;
    if ((unsigned)y < (unsigned)H && (unsigned)x < (unsigned)W) {
        v = (c < C1) ? in1[((size_t)b*C1 + c)*H*W + y*W + x]
                     : in2[((size_t)b*C2 + (c-C1))*H*W + y*W + x];
    }
    dst[(size_t)b*C*Hp*Wp + idx] = v;
}

// ---------------------------------------------------------------------------
// weight prep: fp32 -> bf16 hi/lo, dest[set][stage][co][j], k_lin = stage*64+j
//   mode 0 (conv): t = k_lin / Cin, ci = k_lin % Cin, src = (co*Cin+ci)*9 + t
//   mode 1 (dcn) : src = co*576 + k_lin
// ---------------------------------------------------------------------------
__global__ void prep_w_k(const float* __restrict__ src,
                         __nv_bfloat16* __restrict__ dhi,
                         __nv_bfloat16* __restrict__ dlo,
                         int Cin, int CoutReal, int NPAD, int nstages, int mode,
                         long srcSetStride)
{
    int set = blockIdx.y;
    int total = nstages * NPAD * 64;
    int idx = blockIdx.x * 256 + threadIdx.x;
    if (idx >= total) return;
    int j  = idx & 63;
    int co = (idx >> 6) % NPAD;
    int st = idx / (64 * NPAD);
    int k_lin = st * 64 + j;
    const float* s = src + (size_t)set * srcSetStride;
    float v = 0.f;
    if (co < CoutReal) {
        if (mode == 0) {
            int t = k_lin / Cin, ci = k_lin - t * Cin;
            v = s[((size_t)co * Cin + ci) * 9 + t];
        } else {
            v = s[(size_t)co * 576 + k_lin];
        }
    }
    __nv_bfloat16 hi = __float2bfloat16(v);
    float rem = v - __bfloat162float(hi);
    size_t d = (size_t)set * total + idx;
    dhi[d] = hi;
    dlo[d] = __float2bfloat16(rem);
}

// ---------------------------------------------------------------------------
// mma_gemm: CTA computes D[128 px, 64 outs] (out chunk via blockIdx.z).
// 256 threads / 8 warps; warp w owns rows [16w,16w+16).
// smem: A hi 16K @0, A lo 16K @16384, B hi 8K @32768, B lo 8K @40960.
// ---------------------------------------------------------------------------
__global__ __launch_bounds__(256)
void mma_gemm_k(const float* __restrict__ A,
                const __nv_bfloat16* __restrict__ Whi,
                const __nv_bfloat16* __restrict__ Wlo,
                const float* __restrict__ bias,
                float* __restrict__ out,
                int H, int W, int Cg, int ntaps,
                int NPAD, int Nout, int mode, int act)
{
    extern __shared__ char smem[];
    const uint32_t sb   = smem_u32(smem);
    const uint32_t A_HI = sb;
    const uint32_t A_LO = sb + 16384;
    const uint32_t B_HI = sb + 32768;
    const uint32_t B_LO = sb + 40960;

    const int HW = H * W;
    const int Hp = H + 2, Wp = W + 2;
    const int blocksPerImg = HW / 128;
    const int b   = blockIdx.x / blocksPerImg;
    const int pxb = (blockIdx.x % blocksPerImg) * 128;
    const int co0 = blockIdx.z * 64;
    const int tid  = threadIdx.x;
    const int warp = tid >> 5, lane = tid & 31;
    const int row  = tid & 127, half = tid >> 7;     // staging role
    const int p = pxb + row;
    const int y = p / W, x = p - y * W;
    const int nstages = ntaps * Cg;

    float c[8][4];
#pragma unroll
    for (int i = 0; i < 8; i++)
#pragma unroll
        for (int j = 0; j < 4; j++) c[i][j] = 0.f;

    const float* Ab;
    size_t chStride;
    if (mode == 0) {
        Ab = A + (size_t)b * (Cg * 64) * Hp * Wp;
        chStride = (size_t)Hp * Wp;
    } else {
        Ab = A + (size_t)b * (nstages * 64) * HW + p;
        chStride = (size_t)HW;
    }

    const int m0 = warp * 16;
    // A-fragment lane addressing (m16n8k16, ldmatrix.x4)
    const uint32_t a_row = (uint32_t)(m0 + (lane & 7) + ((lane >> 3) & 1) * 8);
    const uint32_t a_kb  = (uint32_t)(((lane >> 4) & 1) * 16);
    // B-fragment lane addressing (two n-blocks per ldmatrix.x4)
    const uint32_t b_rowbase = (uint32_t)((lane & 7) + ((lane >> 4) & 1) * 8);
    const uint32_t b_kb      = (uint32_t)(((lane >> 3) & 1) * 16);

    for (int s = 0; s < nstages; s++) {
        __syncthreads();
        // ---- stage A: thread handles 32 channels of its pixel row ----
        {
            const float* ap;
            if (mode == 0) {
                int t = s / Cg, cg = s - t * Cg;
                ap = Ab + (size_t)(cg * 64) * chStride
                        + (size_t)(y + t/3) * Wp + (x + t%3);
            } else {
                ap = Ab + (size_t)(s * 64) * chStride;
            }
            int j0 = half * 32;
#pragma unroll 4
            for (int j = j0; j < j0 + 32; j += 2) {
                float v0 = __ldg(ap + (size_t)j * chStride);
                float v1 = __ldg(ap + (size_t)(j+1) * chStride);
                __nv_bfloat16 h0 = __float2bfloat16(v0);
                __nv_bfloat16 h1 = __float2bfloat16(v1);
                __nv_bfloat16 l0 = __float2bfloat16(v0 - __bfloat162float(h0));
                __nv_bfloat16 l1 = __float2bfloat16(v1 - __bfloat162float(h1));
                uint32_t hp = (uint32_t)__bfloat16_as_ushort(h0)
                            | ((uint32_t)__bfloat16_as_ushort(h1) << 16);
                uint32_t lp = (uint32_t)__bfloat16_as_ushort(l0)
                            | ((uint32_t)__bfloat16_as_ushort(l1) << 16);
                uint32_t off = SWZ128((uint32_t)(row*128 + j*2));
                asm volatile("st.shared.b32 [%0], %1;" :: "r"(A_HI + off), "r"(hp));
                asm volatile("st.shared.b32 [%0], %1;" :: "r"(A_LO + off), "r"(lp));
            }
        }
        // ---- stage B: 64 rows x 64 cols bf16 (hi+lo), 2048 pairs each ----
        {
            const __nv_bfloat16* wh = Whi + (size_t)s*NPAD*64 + (size_t)co0*64;
            const __nv_bfloat16* wl = Wlo + (size_t)s*NPAD*64 + (size_t)co0*64;
#pragma unroll
            for (int e = tid; e < 2048; e += 256) {
                int lin = e * 2;
                int co = lin >> 6, j = lin & 63;
                uint32_t hp = *reinterpret_cast<const uint32_t*>(wh + lin);
                uint32_t lp = *reinterpret_cast<const uint32_t*>(wl + lin);
                uint32_t off = SWZ128((uint32_t)(co*128 + j*2));
                asm volatile("st.shared.b32 [%0], %1;" :: "r"(B_HI + off), "r"(hp));
                asm volatile("st.shared.b32 [%0], %1;" :: "r"(B_LO + off), "r"(lp));
            }
        }
        __syncthreads();

        // ---- compute: 4 k-chunks of 16 ----
#pragma unroll
        for (int kc = 0; kc < 4; kc++) {
            uint32_t ah[4], al[4];
            uint32_t aoff = SWZ128(a_row*128 + (uint32_t)kc*32 + a_kb);
            ldm4(ah, A_HI + aoff);
            ldm4(al, A_LO + aoff);
#pragma unroll
            for (int nbp = 0; nbp < 4; nbp++) {
                uint32_t brow = (uint32_t)(nbp*16) + b_rowbase;
                uint32_t boff = SWZ128(brow*128 + (uint32_t)kc*32 + b_kb);
                uint32_t bh[4], bl[4];
                ldm4(bh, B_HI + boff);
                ldm4(bl, B_LO + boff);
                mma16816(c[2*nbp],   ah, bh[0], bh[1]);
                mma16816(c[2*nbp],   ah, bl[0], bl[1]);
                mma16816(c[2*nbp],   al, bh[0], bh[1]);
                mma16816(c[2*nbp+1], ah, bh[2], bh[3]);
                mma16816(c[2*nbp+1], ah, bl[2], bl[3]);
                mma16816(c[2*nbp+1], al, bh[2], bh[3]);
            }
        }
    }

    // ---- epilogue ----
    const int mrow = lane >> 2;
    const int ccol = (lane & 3) * 2;
#pragma unroll
    for (int nb = 0; nb < 8; nb++) {
#pragma unroll
        for (int i = 0; i < 4; i++) {
            int rm  = m0 + mrow + ((i >= 2) ? 8 : 0);
            int col = nb*8 + ccol + (i & 1);
            int co  = co0 + col;
            if (co < Nout) {
                float v = c[nb][i] + __ldg(bias + co);
                if (act) v = v >= 0.f ? v : 0.1f*v;
                out[((size_t)b*Nout + co)*HW + pxb + rm] = v;
            }
        }
    }
}

// ---------------------------------------------------------------------------
// bilinear 2x upsample (align_corners=False), * scale
// ---------------------------------------------------------------------------
__global__ void up2_k(const float* __restrict__ in, float* __restrict__ out,
                      int NC, int H, int W, float scale)
{
    const int W2 = 2*W, H2 = 2*H;
    size_t idx = (size_t)blockIdx.x * blockDim.x + threadIdx.x;
    size_t total = (size_t)NC * H2 * W2;
    if (idx >= total) return;
    int x2 = (int)(idx % W2);
    int y2 = (int)((idx / W2) % H2);
    int c  = (int)(idx / ((size_t)W2 * H2));

    float sy = (y2 + 0.5f)*0.5f - 0.5f;
    float sx = (x2 + 0.5f)*0.5f - 0.5f;
    float fy = floorf(sy), fx = floorf(sx);
    float wy = sy - fy,    wx = sx - fx;
    int y0 = (int)fy, x0 = (int)fx;
    int y0c = min(max(y0, 0), H-1), y1c = min(max(y0+1, 0), H-1);
    int x0c = min(max(x0, 0), W-1), x1c = min(max(x0+1, 0), W-1);

    const float* img = in + (size_t)c*H*W;
    float v00 = img[y0c*W + x0c];
    float v01 = img[y0c*W + x1c];
    float v10 = img[y1c*W + x0c];
    float v11 = img[y1c*W + x1c];
    float v = (1.f-wy)*((1.f-wx)*v00 + wx*v01) + wy*((1.f-wx)*v10 + wx*v11);
    out[idx] = v * scale;
}

// ---------------------------------------------------------------------------
// DCN stage 1: modulated deformable bilinear sampling.
// ---------------------------------------------------------------------------
__global__ __launch_bounds__(256)
void dcn_sample_k(const float* __restrict__ x, const float* __restrict__ om,
                  float* __restrict__ samp, int H, int W)
{
    const int HW = H * W;
    const int px = blockIdx.x * 256 + threadIdx.x;
    const int gk = blockIdx.y;
    const int b  = blockIdx.z;
    const int g  = gk / 9, k = gk - g*9;

    const float* omb = om + (size_t)b*216*HW + px;
    float oy = __ldg(omb + (size_t)gk       *HW);
    float ox = __ldg(omb + (size_t)(72 +gk) *HW);
    float mk = __ldg(omb + (size_t)(144+gk) *HW);
    mk = 1.f / (1.f + expf(-mk));

    const int hr = px / W, wc = px - hr*W;
    float py = oy + (float)(k/3 - 1) + (float)hr;
    float pv = ox + (float)(k%3 - 1) + (float)wc;
    float fy = floorf(py), fx = floorf(pv);
    float wy = py - fy,    wx = pv - fx;
    int y0 = (int)fy, x0 = (int)fx;
    int y1 = y0 + 1,  x1 = x0 + 1;
    float vy0 = (y0 >= 0 && y0 < H) ? 1.f : 0.f;
    float vy1 = (y1 >= 0 && y1 < H) ? 1.f : 0.f;
    float vx0 = (x0 >= 0 && x0 < W) ? 1.f : 0.f;
    float vx1 = (x1 >= 0 && x1 < W) ? 1.f : 0.f;
    float b00 = mk * (1.f-wy)*(1.f-wx) * vy0*vx0;
    float b01 = mk * (1.f-wy)*wx       * vy0*vx1;
    float b10 = mk * wy*(1.f-wx)       * vy1*vx0;
    float b11 = mk * wy*wx             * vy1*vx1;
    int cy0 = min(max(y0,0),H-1), cy1 = min(max(y1,0),H-1);
    int cx0 = min(max(x0,0),W-1), cx1 = min(max(x1,0),W-1);
    int o00 = cy0*W + cx0, o01 = cy0*W + cx1;
    int o10 = cy1*W + cx0, o11 = cy1*W + cx1;

    const float* xg = x + ((size_t)b*64 + g*8)*HW;
    float* sp = samp + ((size_t)b*576 + (size_t)(g*8)*9 + k)*HW + px;
#pragma unroll
    for (int cc = 0; cc < 8; cc++) {
        const float* img = xg + (size_t)cc*HW;
        float v = b00*__ldg(img+o00) + b01*__ldg(img+o01)
                + b10*__ldg(img+o10) + b11*__ldg(img+o11);
        sp[(size_t)cc*9*HW] = v;
    }
}

// ---------------------------------------------------------------------------
// host orchestration
// ---------------------------------------------------------------------------
static float* s_pad = nullptr;

static void pad(const float* i1, const float* i2, int B, int C1, int C2, int H, int W)
{
    int n = (C1+C2)*(H+2)*(W+2);
    dim3 g((n + 255)/256, B);
    pad_k<<<g, 256>>>(i1, i2, s_pad, C1, C2, H, W);
}

static void gemm(const float* A, const __nv_bfloat16* wh, const __nv_bfloat16* wl,
                 const float* bias, float* out, int B, int H, int W,
                 int Cg, int ntaps, int NPAD, int Nout, int mode, int act)
{
    cudaFuncSetAttribute(mma_gemm_k, cudaFuncAttributeMaxDynamicSharedMemorySize, 49152);
    dim3 g(B * (H*W/128), 1, NPAD/64);
    mma_gemm_k<<<g, 256, 49152>>>(A, wh, wl, bias, out, H, W, Cg, ntaps,
                                  NPAD, Nout, mode, act);
}

static void up2(const float* in, float* out, int B, int C, int H, int W, float scale)
{
    size_t n = (size_t)B*C*2*H*2*W;
    up2_k<<<(int)((n + 255)/256), 256>>>(in, out, B*C, H, W, scale);
}

extern "C" void kernel_launch(void* const* d_in, const int* in_sizes, int n_in,
                              void* d_out, int out_size)
{
    const float* f1l1 = (const float*)d_in[0];
    const float* f1l2 = (const float*)d_in[1];
    const float* f1l3 = (const float*)d_in[2];
    const float* f2l1 = (const float*)d_in[3];
    const float* f2l2 = (const float*)d_in[4];
    const float* f2l3 = (const float*)d_in[5];
    const float* w128 = (const float*)d_in[6];
    const float* b128 = (const float*)d_in[7];
    const float* w64  = (const float*)d_in[8];
    const float* b64  = (const float*)d_in[9];
    const float* om_w = (const float*)d_in[10];
    const float* om_b = (const float*)d_in[11];
    const float* dw   = (const float*)d_in[12];
    const float* db   = (const float*)d_in[13];
    float* outp = (float*)d_out;

    const int B = in_sizes[0] / (NF*128*128);   // 4

    float *gA,*gB,*gC,*gD,*gUP,*gOM,*gSP,*gL3o,*gL3f,*gL2o,*gL2f;
    cudaGetSymbolAddress((void**)&gA,  g_A);
    cudaGetSymbolAddress((void**)&gB,  g_B);
    cudaGetSymbolAddress((void**)&gC,  g_C);
    cudaGetSymbolAddress((void**)&gD,  g_D);
    cudaGetSymbolAddress((void**)&gUP, g_UP);
    cudaGetSymbolAddress((void**)&gOM, g_OM);
    cudaGetSymbolAddress((void**)&gSP, g_SAMP);
    cudaGetSymbolAddress((void**)&s_pad, g_PAD);
    cudaGetSymbolAddress((void**)&gL3o, g_L3o);
    cudaGetSymbolAddress((void**)&gL3f, g_L3f);
    cudaGetSymbolAddress((void**)&gL2o, g_L2o);
    cudaGetSymbolAddress((void**)&gL2f, g_L2f);

    __nv_bfloat16 *w128h,*w128l,*w64h,*w64l,*womh,*woml,*wdh,*wdl;
    cudaGetSymbolAddress((void**)&w128h, g_W128hi);
    cudaGetSymbolAddress((void**)&w128l, g_W128lo);
    cudaGetSymbolAddress((void**)&w64h,  g_W64hi);
    cudaGetSymbolAddress((void**)&w64l,  g_W64lo);
    cudaGetSymbolAddress((void**)&womh,  g_WOMhi);
    cudaGetSymbolAddress((void**)&woml,  g_WOMlo);
    cudaGetSymbolAddress((void**)&wdh,   g_WDhi);
    cudaGetSymbolAddress((void**)&wdl,   g_WDlo);

    // ---- weight prep ----
    {
        dim3 g1(18*64*64/256, 8);
        prep_w_k<<<g1, 256>>>(w128, w128h, w128l, 128, 64, 64, 18, 0, 64L*128*9);
        dim3 g2(9*64*64/256, 4);
        prep_w_k<<<g2, 256>>>(w64, w64h, w64l, 64, 64, 64, 9, 0, 64L*64*9);
        dim3 g3(9*256*64/256, 4);
        prep_w_k<<<g3, 256>>>(om_w, womh, woml, 64, 216, 256, 9, 0, 216L*64*9);
        dim3 g4(9*64*64/256, 4);
        prep_w_k<<<g4, 256>>>(dw, wdh, wdl, 64, 64, 64, 9, 1, 64L*64*9);
    }

    const size_t W128ST = 18*64*64, W64ST = 9*64*64, WOMST = (size_t)9*256*64, WDST = 9*64*64;
    const size_t B128S = 64, B64S = 64, OMBS = 216, DBS = 64;

    // ---- L3 (32x32) ----
    pad(f1l3, f2l3, B, 64, 64, 32, 32);
    gemm(s_pad, w128h+0*W128ST, w128l+0*W128ST, b128+0*B128S, gA, B, 32, 32, 2, 9, 64, 64, 0, 1);
    pad(gA, nullptr, B, 64, 0, 32, 32);
    gemm(s_pad, w64h+0*W64ST, w64l+0*W64ST, b64+0*B64S, gL3o, B, 32, 32, 1, 9, 64, 64, 0, 1);
    pad(gL3o, nullptr, B, 64, 0, 32, 32);
    gemm(s_pad, womh+0*WOMST, woml+0*WOMST, om_b+0*OMBS, gOM, B, 32, 32, 1, 9, 256, 216, 0, 0);
    { dim3 sg(32*32/256, 72, B); dcn_sample_k<<<sg, 256>>>(f1l3, gOM, gSP, 32, 32); }
    gemm(gSP, wdh+0*WDST, wdl+0*WDST, db+0*DBS, gL3f, B, 32, 32, 9, 1, 64, 64, 1, 1);

    // ---- L2 (64x64) ----
    pad(f1l2, f2l2, B, 64, 64, 64, 64);
    gemm(s_pad, w128h+1*W128ST, w128l+1*W128ST, b128+1*B128S, gA, B, 64, 64, 2, 9, 64, 64, 0, 1);
    up2(gL3o, gUP, B, 64, 32, 32, 2.0f);
    pad(gA, gUP, B, 64, 64, 64, 64);
    gemm(s_pad, w128h+2*W128ST, w128l+2*W128ST, b128+2*B128S, gB, B, 64, 64, 2, 9, 64, 64, 0, 1);
    pad(gB, nullptr, B, 64, 0, 64, 64);
    gemm(s_pad, w64h+1*W64ST, w64l+1*W64ST, b64+1*B64S, gL2o, B, 64, 64, 1, 9, 64, 64, 0, 1);
    pad(gL2o, nullptr, B, 64, 0, 64, 64);
    gemm(s_pad, womh+1*WOMST, woml+1*WOMST, om_b+1*OMBS, gOM, B, 64, 64, 1, 9, 256, 216, 0, 0);
    { dim3 sg(64*64/256, 72, B); dcn_sample_k<<<sg, 256>>>(f1l2, gOM, gSP, 64, 64); }
    gemm(gSP, wdh+1*WDST, wdl+1*WDST, db+1*DBS, gA, B, 64, 64, 9, 1, 64, 64, 1, 0);
    up2(gL3f, gUP, B, 64, 32, 32, 1.0f);
    pad(gA, gUP, B, 64, 64, 64, 64);
    gemm(s_pad, w128h+3*W128ST, w128l+3*W128ST, b128+3*B128S, gL2f, B, 64, 64, 2, 9, 64, 64, 0, 1);

    // ---- L1 (128x128) ----
    pad(f1l1, f2l1, B, 64, 64, 128, 128);
    gemm(s_pad, w128h+4*W128ST, w128l+4*W128ST, b128+4*B128S, gA, B, 128, 128, 2, 9, 64, 64, 0, 1);
    up2(gL2o, gUP, B, 64, 64, 64, 2.0f);
    pad(gA, gUP, B, 64, 64, 128, 128);
    gemm(s_pad, w128h+5*W128ST, w128l+5*W128ST, b128+5*B128S, gB, B, 128, 128, 2, 9, 64, 64, 0, 1);
    pad(gB, nullptr, B, 64, 0, 128, 128);
    gemm(s_pad, w64h+2*W64ST, w64l+2*W64ST, b64+2*B64S, gC, B, 128, 128, 1, 9, 64, 64, 0, 1);
    pad(gC, nullptr, B, 64, 0, 128, 128);
    gemm(s_pad, womh+2*WOMST, woml+2*WOMST, om_b+2*OMBS, gOM, B, 128, 128, 1, 9, 256, 216, 0, 0);
    { dim3 sg(128*128/256, 72, B); dcn_sample_k<<<sg, 256>>>(f1l1, gOM, gSP, 128, 128); }
    gemm(gSP, wdh+2*WDST, wdl+2*WDST, db+2*DBS, gA, B, 128, 128, 9, 1, 64, 64, 1, 0);
    up2(gL2f, gUP, B, 64, 64, 64, 1.0f);
    pad(gA, gUP, B, 64, 64, 128, 128);
    gemm(s_pad, w128h+6*W128ST, w128l+6*W128ST, b128+6*B128S, gD, B, 128, 128, 2, 9, 64, 64, 0, 0);

    // ---- Cascading ----
    pad(gD, f2l1, B, 64, 64, 128, 128);
    gemm(s_pad, w128h+7*W128ST, w128l+7*W128ST, b128+7*B128S, gA, B, 128, 128, 2, 9, 64, 64, 0, 1);
    pad(gA, nullptr, B, 64, 0, 128, 128);
    gemm(s_pad, w64h+3*W64ST, w64l+3*W64ST, b64+3*B64S, gB, B, 128, 128, 1, 9, 64, 64, 0, 1);
    pad(gB, nullptr, B, 64, 0, 128, 128);
    gemm(s_pad, womh+3*WOMST, woml+3*WOMST, om_b+3*OMBS, gOM, B, 128, 128, 1, 9, 256, 216, 0, 0);
    { dim3 sg(128*128/256, 72, B); dcn_sample_k<<<sg, 256>>>(gD, gOM, gSP, 128, 128); }
    gemm(gSP, wdh+3*WDST, wdl+3*WDST, db+3*DBS, outp, B, 128, 128, 9, 1, 64, 64, 1, 1);
}

// round 9
// speedup vs baseline: 3.3134x; 1.1708x over previous
#include <cuda_runtime.h>
#include <cuda_bf16.h>
#include <cstddef>
#include <cstdint>
#include <math.h>

// ---------------------------------------------------------------------------
// PCDAlign via warp-level mma.sync (bf16 hi/lo split, fp32 accum), sm_103.
// R9: cp.async double-buffered GEMM mainloop; activations pre-split to bf16
// hi/lo NHWC (padded) once per conv input; DCN samples emitted as bf16 hi/lo.
// ---------------------------------------------------------------------------

#define NF 64

// ---------------- scratch (B=4 fixed) ----------------
#define L1N (4*64*128*128)
#define L2N (4*64*64*64)
#define L3N (4*64*32*32)
#define OMN (4*216*128*128)
#define PADE (4*130*130*128)          // padded NHWC elems (max C=128)
#define SPE  (4*576*128*128)

__device__ float g_A [L1N];
__device__ float g_B [L1N];
__device__ float g_C [L1N];
__device__ float g_D [L1N];
__device__ float g_UP[L1N];
__device__ float g_OM[OMN];
__device__ float g_L3o[L3N];
__device__ float g_L3f[L3N];
__device__ float g_L2o[L2N];
__device__ float g_L2f[L2N];

__device__ __nv_bfloat16 g_PADH[PADE];
__device__ __nv_bfloat16 g_PADL[PADE];
__device__ __nv_bfloat16 g_SPH [SPE];
__device__ __nv_bfloat16 g_SPL [SPE];

// bf16 split weights: [set][stage][co][64]
__device__ __nv_bfloat16 g_W128hi[8*18*64*64];
__device__ __nv_bfloat16 g_W128lo[8*18*64*64];
__device__ __nv_bfloat16 g_W64hi [4*9*64*64];
__device__ __nv_bfloat16 g_W64lo [4*9*64*64];
__device__ __nv_bfloat16 g_WOMhi [4*9*256*64];
__device__ __nv_bfloat16 g_WOMlo [4*9*256*64];
__device__ __nv_bfloat16 g_WDhi  [4*9*64*64];
__device__ __nv_bfloat16 g_WDlo  [4*9*64*64];

// ---------------- helpers ----------------
__device__ __forceinline__ uint32_t smem_u32(const void* p) {
    uint32_t a;
    asm("{ .reg .u64 t; cvta.to.shared.u64 t, %1; cvt.u32.u64 %0, t; }"
        : "=r"(a) : "l"(p));
    return a;
}
#define SWZ128(off) ((off) ^ (((off) >> 3) & 0x70))

__device__ __forceinline__ void ldm4(uint32_t r[4], uint32_t addr) {
    asm volatile("ldmatrix.sync.aligned.m8n8.x4.shared.b16 {%0,%1,%2,%3}, [%4];"
        : "=r"(r[0]), "=r"(r[1]), "=r"(r[2]), "=r"(r[3]) : "r"(addr));
}
__device__ __forceinline__ void mma16816(float c[4], const uint32_t a[4],
                                         uint32_t b0, uint32_t b1) {
    asm volatile(
        "mma.sync.aligned.m16n8k16.row.col.f32.bf16.bf16.f32 "
        "{%0,%1,%2,%3}, {%4,%5,%6,%7}, {%8,%9}, {%0,%1,%2,%3};"
        : "+f"(c[0]), "+f"(c[1]), "+f"(c[2]), "+f"(c[3])
        : "r"(a[0]), "r"(a[1]), "r"(a[2]), "r"(a[3]), "r"(b0), "r"(b1));
}
__device__ __forceinline__ void cp16(uint32_t dst, const void* src) {
    asm volatile("cp.async.cg.shared.global [%0], [%1], 16;" :: "r"(dst), "l"(src));
}
#define CP_COMMIT() asm volatile("cp.async.commit_group;" ::: "memory")
#define CP_WAIT1()  asm volatile("cp.async.wait_group 1;" ::: "memory")
#define CP_WAIT0()  asm volatile("cp.async.wait_group 0;" ::: "memory")

// ---------------------------------------------------------------------------
// pad: concat(in1,in2) NCHW fp32 -> padded NHWC bf16 hi/lo (zero border).
// Block handles 32 consecutive padded pixels; smem transpose for coalescing.
// ---------------------------------------------------------------------------
__global__ __launch_bounds__(256)
void pad_k(const float* __restrict__ in1, const float* __restrict__ in2,
           __nv_bfloat16* __restrict__ outH, __nv_bfloat16* __restrict__ outL,
           int C1, int C2, int H, int W)
{
    const int C = C1 + C2, Hp = H + 2, Wp = W + 2;
    const int b = blockIdx.y;
    const int p0 = blockIdx.x * 32;
    const int tid = threadIdx.x;

    __shared__ float tile[128][33];

    // read phase: warp w reads channel (it*8 + w) for 32 pixels
    {
        int i = tid & 31;
        int pidx = p0 + i;
        int yp = pidx / Wp, xp = pidx - yp * Wp;
        int y = yp - 1, x = xp - 1;
        bool valid = (pidx < Hp*Wp) &&
                     (unsigned)y < (unsigned)H && (unsigned)x < (unsigned)W;
        int w = tid >> 5;
        for (int it = 0; it < C/8; it++) {
            int c = it*8 + w;
            float v = 0.f;
            if (valid)
                v = (c < C1) ? in1[((size_t)b*C1 + c)*H*W + y*W + x]
                             : in2[((size_t)b*C2 + (c-C1))*H*W + y*W + x];
            tile[c][i] = v;
        }
    }
    __syncthreads();
    // write phase: per iter, 256/C pixels x C channels, contiguous stores
    {
        int pxPerIter = 256 / C;
        int c = tid % C, psub = tid / C;
        for (int it = 0; it < 32/pxPerIter; it++) {
            int ii = it*pxPerIter + psub;
            int pp = p0 + ii;
            if (pp < Hp*Wp) {
                float v = tile[c][ii];
                __nv_bfloat16 h = __float2bfloat16(v);
                size_t o = ((size_t)b*Hp*Wp + pp)*C + c;
                outH[o] = h;
                outL[o] = __float2bfloat16(v - __bfloat162float(h));
            }
        }
    }
}

// ---------------------------------------------------------------------------
// weight prep: fp32 -> bf16 hi/lo, dest[set][stage][co][64]
// ---------------------------------------------------------------------------
__global__ void prep_w_k(const float* __restrict__ src,
                         __nv_bfloat16* __restrict__ dhi,
                         __nv_bfloat16* __restrict__ dlo,
                         int Cin, int CoutReal, int NPAD, int nstages, int mode,
                         long srcSetStride)
{
    int set = blockIdx.y;
    int total = nstages * NPAD * 64;
    int idx = blockIdx.x * 256 + threadIdx.x;
    if (idx >= total) return;
    int j  = idx & 63;
    int co = (idx >> 6) % NPAD;
    int st = idx / (64 * NPAD);
    int k_lin = st * 64 + j;
    const float* s = src + (size_t)set * srcSetStride;
    float v = 0.f;
    if (co < CoutReal) {
        if (mode == 0) {
            int t = k_lin / Cin, ci = k_lin - t * Cin;
            v = s[((size_t)co * Cin + ci) * 9 + t];
        } else {
            v = s[(size_t)co * 576 + k_lin];
        }
    }
    __nv_bfloat16 hi = __float2bfloat16(v);
    float rem = v - __bfloat162float(hi);
    size_t d = (size_t)set * total + idx;
    dhi[d] = hi;
    dlo[d] = __float2bfloat16(rem);
}

// ---------------------------------------------------------------------------
// mma_gemm: CTA computes D[128 px, 64 outs] (out chunk via blockIdx.z).
// 256 threads / 8 warps. Per 48KB stage buffer: A hi 16K, A lo 16K,
// B hi 8K, B lo 8K. mode0: cp.async 2-deep pipeline; mode1: sync staging.
// ---------------------------------------------------------------------------
__global__ __launch_bounds__(256)
void mma_gemm_k(const __nv_bfloat16* __restrict__ Ah,
                const __nv_bfloat16* __restrict__ Al,
                const __nv_bfloat16* __restrict__ Whi,
                const __nv_bfloat16* __restrict__ Wlo,
                const float* __restrict__ bias,
                float* __restrict__ out,
                int H, int W, int Cg, int ntaps,
                int NPAD, int Nout, int mode, int act)
{
    extern __shared__ char smem[];
    const uint32_t sb = smem_u32(smem);

    const int HW = H * W;
    const int Hp = H + 2, Wp = W + 2;
    const int Cpad = Cg * 64;
    const int blocksPerImg = HW / 128;
    const int b   = blockIdx.x / blocksPerImg;
    const int pxb = (blockIdx.x % blocksPerImg) * 128;
    const int co0 = blockIdx.z * 64;
    const int tid  = threadIdx.x;
    const int warp = tid >> 5, lane = tid & 31;
    const int row  = tid & 127, half = tid >> 7;
    const int p = pxb + row;
    const int y = p / W, x = p - y * W;
    const int nstages = ntaps * Cg;

    float c[8][4];
#pragma unroll
    for (int i = 0; i < 8; i++)
#pragma unroll
        for (int j = 0; j < 4; j++) c[i][j] = 0.f;

    const __nv_bfloat16* Apix = half ? Al : Ah;       // this thread stages hi or lo
    const int m0 = warp * 16;
    const uint32_t a_row = (uint32_t)(m0 + (lane & 7) + ((lane >> 3) & 1) * 8);
    const uint32_t a_kb  = (uint32_t)(((lane >> 4) & 1) * 16);
    const uint32_t b_rowbase = (uint32_t)((lane & 7) + ((lane >> 4) & 1) * 8);
    const uint32_t b_kb      = (uint32_t)(((lane >> 3) & 1) * 16);

    // ---- staging issue (mode 0, cp.async) ----
    auto issue_stage = [&](int s, uint32_t bufb) {
        // A: this thread's pixel row, 8 x 16B
        int t, cg;
        if (Cg == 2) { t = s >> 1; cg = s & 1; } else { t = s; cg = 0; }
        const __nv_bfloat16* src = Apix
            + ((size_t)((b*Hp + y + t/3))*Wp + (x + t%3))*Cpad + cg*64;
        uint32_t abase = bufb + (half ? 16384u : 0u);
#pragma unroll
        for (int q = 0; q < 8; q++) {
            uint32_t dst = abase + SWZ128((uint32_t)(row*128 + q*16));
            cp16(dst, src + q*8);
        }
        // B: 1024 x 16B chunks (512 hi, 512 lo), 4 per thread
        const __nv_bfloat16* wh = Whi + (size_t)s*NPAD*64 + (size_t)co0*64;
        const __nv_bfloat16* wl = Wlo + (size_t)s*NPAD*64 + (size_t)co0*64;
#pragma unroll
        for (int q = 0; q < 4; q++) {
            int e = tid*4 + q;
            int lo = e >> 9;            // 0: hi, 1: lo
            int ee = e & 511;
            int r = ee >> 3, ch = ee & 7;
            const __nv_bfloat16* wsrc = (lo ? wl : wh) + r*64 + ch*8;
            uint32_t dst = bufb + (lo ? 40960u : 32768u)
                         + SWZ128((uint32_t)(r*128 + ch*16));
            cp16(dst, wsrc);
        }
    };

    // ---- compute one staged buffer ----
    auto compute = [&](uint32_t bufb) {
        const uint32_t A_HI = bufb, A_LO = bufb + 16384;
        const uint32_t B_HI = bufb + 32768, B_LO = bufb + 40960;
#pragma unroll
        for (int kc = 0; kc < 4; kc++) {
            uint32_t ah[4], al[4];
            uint32_t aoff = SWZ128(a_row*128 + (uint32_t)kc*32 + a_kb);
            ldm4(ah, A_HI + aoff);
            ldm4(al, A_LO + aoff);
#pragma unroll
            for (int nbp = 0; nbp < 4; nbp++) {
                uint32_t brow = (uint32_t)(nbp*16) + b_rowbase;
                uint32_t boff = SWZ128(brow*128 + (uint32_t)kc*32 + b_kb);
                uint32_t bh[4], bl[4];
                ldm4(bh, B_HI + boff);
                ldm4(bl, B_LO + boff);
                mma16816(c[2*nbp],   ah, bh[0], bh[1]);
                mma16816(c[2*nbp],   ah, bl[0], bl[1]);
                mma16816(c[2*nbp],   al, bh[0], bh[1]);
                mma16816(c[2*nbp+1], ah, bh[2], bh[3]);
                mma16816(c[2*nbp+1], ah, bl[2], bl[3]);
                mma16816(c[2*nbp+1], al, bh[2], bh[3]);
            }
        }
    };

    if (mode == 0) {
        issue_stage(0, sb);
        CP_COMMIT();
        for (int s = 0; s < nstages; s++) {
            uint32_t cur = sb + (uint32_t)(s & 1)*49152u;
            if (s + 1 < nstages) {
                issue_stage(s + 1, sb + (uint32_t)((s+1) & 1)*49152u);
                CP_COMMIT();
                CP_WAIT1();
            } else {
                CP_WAIT0();
            }
            __syncthreads();
            compute(cur);
            __syncthreads();
        }
    } else {
        // DCN: A = samp bf16 hi/lo, [b][576][HW]; synchronous staging, buf 0
        const __nv_bfloat16* base = (half ? g_SPL : g_SPH);
        for (int s = 0; s < nstages; s++) {
            __syncthreads();
            {
                const __nv_bfloat16* src = base + ((size_t)b*576 + s*64)*HW + p;
                uint32_t abase = sb + (half ? 16384u : 0u);
#pragma unroll 8
                for (int j = 0; j < 64; j += 2) {
                    uint16_t v0 = *reinterpret_cast<const uint16_t*>(src + (size_t)j*HW);
                    uint16_t v1 = *reinterpret_cast<const uint16_t*>(src + (size_t)(j+1)*HW);
                    uint32_t pk = (uint32_t)v0 | ((uint32_t)v1 << 16);
                    uint32_t off = SWZ128((uint32_t)(row*128 + j*2));
                    asm volatile("st.shared.b32 [%0], %1;" :: "r"(abase + off), "r"(pk));
                }
                const __nv_bfloat16* wh = Whi + (size_t)s*NPAD*64;
                const __nv_bfloat16* wl = Wlo + (size_t)s*NPAD*64;
#pragma unroll
                for (int e = tid; e < 2048; e += 256) {
                    int lin = e * 2;
                    int co = lin >> 6, j = lin & 63;
                    uint32_t hp = *reinterpret_cast<const uint32_t*>(wh + lin);
                    uint32_t lp = *reinterpret_cast<const uint32_t*>(wl + lin);
                    uint32_t off = SWZ128((uint32_t)(co*128 + j*2));
                    asm volatile("st.shared.b32 [%0], %1;" :: "r"(sb + 32768u + off), "r"(hp));
                    asm volatile("st.shared.b32 [%0], %1;" :: "r"(sb + 40960u + off), "r"(lp));
                }
            }
            __syncthreads();
            compute(sb);
        }
    }

    // ---- epilogue ----
    const int mrow = lane >> 2;
    const int ccol = (lane & 3) * 2;
#pragma unroll
    for (int nb = 0; nb < 8; nb++) {
#pragma unroll
        for (int i = 0; i < 4; i++) {
            int rm  = m0 + mrow + ((i >= 2) ? 8 : 0);
            int col = nb*8 + ccol + (i & 1);
            int co  = co0 + col;
            if (co < Nout) {
                float v = c[nb][i] + __ldg(bias + co);
                if (act) v = v >= 0.f ? v : 0.1f*v;
                out[((size_t)b*Nout + co)*HW + pxb + rm] = v;
            }
        }
    }
}

// ---------------------------------------------------------------------------
// bilinear 2x upsample (align_corners=False), * scale
// ---------------------------------------------------------------------------
__global__ void up2_k(const float* __restrict__ in, float* __restrict__ out,
                      int NC, int H, int W, float scale)
{
    const int W2 = 2*W, H2 = 2*H;
    size_t idx = (size_t)blockIdx.x * blockDim.x + threadIdx.x;
    size_t total = (size_t)NC * H2 * W2;
    if (idx >= total) return;
    int x2 = (int)(idx % W2);
    int y2 = (int)((idx / W2) % H2);
    int c  = (int)(idx / ((size_t)W2 * H2));

    float sy = (y2 + 0.5f)*0.5f - 0.5f;
    float sx = (x2 + 0.5f)*0.5f - 0.5f;
    float fy = floorf(sy), fx = floorf(sx);
    float wy = sy - fy,    wx = sx - fx;
    int y0 = (int)fy, x0 = (int)fx;
    int y0c = min(max(y0, 0), H-1), y1c = min(max(y0+1, 0), H-1);
    int x0c = min(max(x0, 0), W-1), x1c = min(max(x0+1, 0), W-1);

    const float* img = in + (size_t)c*H*W;
    float v00 = img[y0c*W + x0c];
    float v01 = img[y0c*W + x1c];
    float v10 = img[y1c*W + x0c];
    float v11 = img[y1c*W + x1c];
    float v = (1.f-wy)*((1.f-wx)*v00 + wx*v01) + wy*((1.f-wx)*v10 + wx*v11);
    out[idx] = v * scale;
}

// ---------------------------------------------------------------------------
// DCN stage 1: modulated deformable bilinear sampling -> bf16 hi/lo
// ---------------------------------------------------------------------------
__global__ __launch_bounds__(256)
void dcn_sample_k(const float* __restrict__ x, const float* __restrict__ om,
                  __nv_bfloat16* __restrict__ sph, __nv_bfloat16* __restrict__ spl,
                  int H, int W)
{
    const int HW = H * W;
    const int px = blockIdx.x * 256 + threadIdx.x;
    const int gk = blockIdx.y;
    const int b  = blockIdx.z;
    const int g  = gk / 9, k = gk - g*9;

    const float* omb = om + (size_t)b*216*HW + px;
    float oy = __ldg(omb + (size_t)gk       *HW);
    float ox = __ldg(omb + (size_t)(72 +gk) *HW);
    float mk = __ldg(omb + (size_t)(144+gk) *HW);
    mk = 1.f / (1.f + expf(-mk));

    const int hr = px / W, wc = px - hr*W;
    float py = oy + (float)(k/3 - 1) + (float)hr;
    float pv = ox + (float)(k%3 - 1) + (float)wc;
    float fy = floorf(py), fx = floorf(pv);
    float wy = py - fy,    wx = pv - fx;
    int y0 = (int)fy, x0 = (int)fx;
    int y1 = y0 + 1,  x1 = x0 + 1;
    float vy0 = (y0 >= 0 && y0 < H) ? 1.f : 0.f;
    float vy1 = (y1 >= 0 && y1 < H) ? 1.f : 0.f;
    float vx0 = (x0 >= 0 && x0 < W) ? 1.f : 0.f;
    float vx1 = (x1 >= 0 && x1 < W) ? 1.f : 0.f;
    float b00 = mk * (1.f-wy)*(1.f-wx) * vy0*vx0;
    float b01 = mk * (1.f-wy)*wx       * vy0*vx1;
    float b10 = mk * wy*(1.f-wx)       * vy1*vx0;
    float b11 = mk * wy*wx             * vy1*vx1;
    int cy0 = min(max(y0,0),H-1), cy1 = min(max(y1,0),H-1);
    int cx0 = min(max(x0,0),W-1), cx1 = min(max(x1,0),W-1);
    int o00 = cy0*W + cx0, o01 = cy0*W + cx1;
    int o10 = cy1*W + cx0, o11 = cy1*W + cx1;

    const float* xg = x + ((size_t)b*64 + g*8)*HW;
    size_t base = ((size_t)b*576 + (size_t)(g*8)*9 + k)*HW + px;
#pragma unroll
    for (int cc = 0; cc < 8; cc++) {
        const float* img = xg + (size_t)cc*HW;
        float v = b00*__ldg(img+o00) + b01*__ldg(img+o01)
                + b10*__ldg(img+o10) + b11*__ldg(img+o11);
        __nv_bfloat16 h = __float2bfloat16(v);
        size_t o = base + (size_t)cc*9*HW;
        sph[o] = h;
        spl[o] = __float2bfloat16(v - __bfloat162float(h));
    }
}

// ---------------------------------------------------------------------------
// host orchestration
// ---------------------------------------------------------------------------
static __nv_bfloat16 *s_padH = nullptr, *s_padL = nullptr;
static __nv_bfloat16 *s_spH = nullptr, *s_spL = nullptr;

static void pad(const float* i1, const float* i2, int B, int C1, int C2, int H, int W)
{
    int Hp = H+2, Wp = W+2;
    dim3 g((Hp*Wp + 31)/32, B);
    pad_k<<<g, 256>>>(i1, i2, s_padH, s_padL, C1, C2, H, W);
}

static void gemm_conv(const __nv_bfloat16* wh, const __nv_bfloat16* wl,
                      const float* bias, float* out, int B, int H, int W,
                      int Cg, int NPAD, int Nout, int act)
{
    dim3 g(B * (H*W/128), 1, NPAD/64);
    mma_gemm_k<<<g, 256, 98304>>>(s_padH, s_padL, wh, wl, bias, out,
                                  H, W, Cg, 9, NPAD, Nout, 0, act);
}

static void gemm_dcn(const __nv_bfloat16* wh, const __nv_bfloat16* wl,
                     const float* bias, float* out, int B, int H, int W, int act)
{
    dim3 g(B * (H*W/128), 1, 1);
    mma_gemm_k<<<g, 256, 49152>>>(s_spH, s_spL, wh, wl, bias, out,
                                  H, W, 9, 1, 64, 64, 1, act);
}

static void up2(const float* in, float* out, int B, int C, int H, int W, float scale)
{
    size_t n = (size_t)B*C*2*H*2*W;
    up2_k<<<(int)((n + 255)/256), 256>>>(in, out, B*C, H, W, scale);
}

extern "C" void kernel_launch(void* const* d_in, const int* in_sizes, int n_in,
                              void* d_out, int out_size)
{
    const float* f1l1 = (const float*)d_in[0];
    const float* f1l2 = (const float*)d_in[1];
    const float* f1l3 = (const float*)d_in[2];
    const float* f2l1 = (const float*)d_in[3];
    const float* f2l2 = (const float*)d_in[4];
    const float* f2l3 = (const float*)d_in[5];
    const float* w128 = (const float*)d_in[6];
    const float* b128 = (const float*)d_in[7];
    const float* w64  = (const float*)d_in[8];
    const float* b64  = (const float*)d_in[9];
    const float* om_w = (const float*)d_in[10];
    const float* om_b = (const float*)d_in[11];
    const float* dw   = (const float*)d_in[12];
    const float* db   = (const float*)d_in[13];
    float* outp = (float*)d_out;

    const int B = in_sizes[0] / (NF*128*128);   // 4

    float *gA,*gB,*gC,*gD,*gUP,*gOM,*gL3o,*gL3f,*gL2o,*gL2f;
    cudaGetSymbolAddress((void**)&gA,  g_A);
    cudaGetSymbolAddress((void**)&gB,  g_B);
    cudaGetSymbolAddress((void**)&gC,  g_C);
    cudaGetSymbolAddress((void**)&gD,  g_D);
    cudaGetSymbolAddress((void**)&gUP, g_UP);
    cudaGetSymbolAddress((void**)&gOM, g_OM);
    cudaGetSymbolAddress((void**)&gL3o, g_L3o);
    cudaGetSymbolAddress((void**)&gL3f, g_L3f);
    cudaGetSymbolAddress((void**)&gL2o, g_L2o);
    cudaGetSymbolAddress((void**)&gL2f, g_L2f);
    cudaGetSymbolAddress((void**)&s_padH, g_PADH);
    cudaGetSymbolAddress((void**)&s_padL, g_PADL);
    cudaGetSymbolAddress((void**)&s_spH,  g_SPH);
    cudaGetSymbolAddress((void**)&s_spL,  g_SPL);

    __nv_bfloat16 *w128h,*w128l,*w64h,*w64l,*womh,*woml,*wdh,*wdl;
    cudaGetSymbolAddress((void**)&w128h, g_W128hi);
    cudaGetSymbolAddress((void**)&w128l, g_W128lo);
    cudaGetSymbolAddress((void**)&w64h,  g_W64hi);
    cudaGetSymbolAddress((void**)&w64l,  g_W64lo);
    cudaGetSymbolAddress((void**)&womh,  g_WOMhi);
    cudaGetSymbolAddress((void**)&woml,  g_WOMlo);
    cudaGetSymbolAddress((void**)&wdh,   g_WDhi);
    cudaGetSymbolAddress((void**)&wdl,   g_WDlo);

    cudaFuncSetAttribute(mma_gemm_k, cudaFuncAttributeMaxDynamicSharedMemorySize, 98304);

    // ---- weight prep ----
    {
        dim3 g1(18*64*64/256, 8);
        prep_w_k<<<g1, 256>>>(w128, w128h, w128l, 128, 64, 64, 18, 0, 64L*128*9);
        dim3 g2(9*64*64/256, 4);
        prep_w_k<<<g2, 256>>>(w64, w64h, w64l, 64, 64, 64, 9, 0, 64L*64*9);
        dim3 g3(9*256*64/256, 4);
        prep_w_k<<<g3, 256>>>(om_w, womh, woml, 64, 216, 256, 9, 0, 216L*64*9);
        dim3 g4(9*64*64/256, 4);
        prep_w_k<<<g4, 256>>>(dw, wdh, wdl, 64, 64, 64, 9, 1, 64L*64*9);
    }

    const size_t W128ST = 18*64*64, W64ST = 9*64*64, WOMST = (size_t)9*256*64, WDST = 9*64*64;
    const size_t B128S = 64, B64S = 64, OMBS = 216, DBS = 64;

    // ---- L3 (32x32) ----
    pad(f1l3, f2l3, B, 64, 64, 32, 32);
    gemm_conv(w128h+0*W128ST, w128l+0*W128ST, b128+0*B128S, gA, B, 32, 32, 2, 64, 64, 1);
    pad(gA, nullptr, B, 64, 0, 32, 32);
    gemm_conv(w64h+0*W64ST, w64l+0*W64ST, b64+0*B64S, gL3o, B, 32, 32, 1, 64, 64, 1);
    pad(gL3o, nullptr, B, 64, 0, 32, 32);
    gemm_conv(womh+0*WOMST, woml+0*WOMST, om_b+0*OMBS, gOM, B, 32, 32, 1, 256, 216, 0);
    { dim3 sg(32*32/256, 72, B); dcn_sample_k<<<sg, 256>>>(f1l3, gOM, s_spH, s_spL, 32, 32); }
    gemm_dcn(wdh+0*WDST, wdl+0*WDST, db+0*DBS, gL3f, B, 32, 32, 1);

    // ---- L2 (64x64) ----
    pad(f1l2, f2l2, B, 64, 64, 64, 64);
    gemm_conv(w128h+1*W128ST, w128l+1*W128ST, b128+1*B128S, gA, B, 64, 64, 2, 64, 64, 1);
    up2(gL3o, gUP, B, 64, 32, 32, 2.0f);
    pad(gA, gUP, B, 64, 64, 64, 64);
    gemm_conv(w128h+2*W128ST, w128l+2*W128ST, b128+2*B128S, gB, B, 64, 64, 2, 64, 64, 1);
    pad(gB, nullptr, B, 64, 0, 64, 64);
    gemm_conv(w64h+1*W64ST, w64l+1*W64ST, b64+1*B64S, gL2o, B, 64, 64, 1, 64, 64, 1);
    pad(gL2o, nullptr, B, 64, 0, 64, 64);
    gemm_conv(womh+1*WOMST, woml+1*WOMST, om_b+1*OMBS, gOM, B, 64, 64, 1, 256, 216, 0);
    { dim3 sg(64*64/256, 72, B); dcn_sample_k<<<sg, 256>>>(f1l2, gOM, s_spH, s_spL, 64, 64); }
    gemm_dcn(wdh+1*WDST, wdl+1*WDST, db+1*DBS, gA, B, 64, 64, 0);
    up2(gL3f, gUP, B, 64, 32, 32, 1.0f);
    pad(gA, gUP, B, 64, 64, 64, 64);
    gemm_conv(w128h+3*W128ST, w128l+3*W128ST, b128+3*B128S, gL2f, B, 64, 64, 2, 64, 64, 1);

    // ---- L1 (128x128) ----
    pad(f1l1, f2l1, B, 64, 64, 128, 128);
    gemm_conv(w128h+4*W128ST, w128l+4*W128ST, b128+4*B128S, gA, B, 128, 128, 2, 64, 64, 1);
    up2(gL2o, gUP, B, 64, 64, 64, 2.0f);
    pad(gA, gUP, B, 64, 64, 128, 128);
    gemm_conv(w128h+5*W128ST, w128l+5*W128ST, b128+5*B128S, gB, B, 128, 128, 2, 64, 64, 1);
    pad(gB, nullptr, B, 64, 0, 128, 128);
    gemm_conv(w64h+2*W64ST, w64l+2*W64ST, b64+2*B64S, gC, B, 128, 128, 1, 64, 64, 1);
    pad(gC, nullptr, B, 64, 0, 128, 128);
    gemm_conv(womh+2*WOMST, woml+2*WOMST, om_b+2*OMBS, gOM, B, 128, 128, 1, 256, 216, 0);
    { dim3 sg(128*128/256, 72, B); dcn_sample_k<<<sg, 256>>>(f1l1, gOM, s_spH, s_spL, 128, 128); }
    gemm_dcn(wdh+2*WDST, wdl+2*WDST, db+2*DBS, gA, B, 128, 128, 0);
    up2(gL2f, gUP, B, 64, 64, 64, 1.0f);
    pad(gA, gUP, B, 64, 64, 128, 128);
    gemm_conv(w128h+6*W128ST, w128l+6*W128ST, b128+6*B128S, gD, B, 128, 128, 2, 64, 64, 0);

    // ---- Cascading ----
    pad(gD, f2l1, B, 64, 64, 128, 128);
    gemm_conv(w128h+7*W128ST, w128l+7*W128ST, b128+7*B128S, gA, B, 128, 128, 2, 64, 64, 1);
    pad(gA, nullptr, B, 64, 0, 128, 128);
    gemm_conv(w64h+3*W64ST, w64l+3*W64ST, b64+3*B64S, gB, B, 128, 128, 1, 64, 64, 1);
    pad(gB, nullptr, B, 64, 0, 128, 128);
    gemm_conv(womh+3*WOMST, woml+3*WOMST, om_b+3*OMBS, gOM, B, 128, 128, 1, 256, 216, 0);
    { dim3 sg(128*128/256, 72, B); dcn_sample_k<<<sg, 256>>>(gD, gOM, s_spH, s_spL, 128, 128); }
    gemm_dcn(wdh+3*WDST, wdl+3*WDST, db+3*DBS, outp, B, 128, 128, 1);
}